// round 1
// baseline (speedup 1.0000x reference)
#include <cuda_runtime.h>

// Problem constants (fixed shapes from setup_inputs)
#define B    16
#define CIN  256
#define COUT 128
#define SDIM 512
#define HIN  64
#define H129 129
#define HOUT 128

// Scratch (module-load allocated, allowed)
__device__ float g_s[B * CIN];                       // modulated style (B, Cin)
__device__ float g_w[B * 9 * CIN * COUT];            // weights [b][tap(ky*3+kx)][ci][co]
__device__ float g_o[(size_t)B * COUT * H129 * H129]; // transposed-conv intermediate

// ---------------------------------------------------------------------------
// Stage 1: s[b,ci] = sum_k style[b,k]*mod_w[ci,k] + mod_b[ci]
// ---------------------------------------------------------------------------
__global__ void k_style(const float* __restrict__ style,
                        const float* __restrict__ mod_w,
                        const float* __restrict__ mod_b) {
    int b = blockIdx.x;
    int warp = threadIdx.x >> 5, lane = threadIdx.x & 31;
    const float* st = style + b * SDIM;
    for (int ci = warp; ci < CIN; ci += 8) {
        const float* mw = mod_w + ci * SDIM;
        float sum = 0.f;
        for (int k = lane; k < SDIM; k += 32) sum += st[k] * mw[k];
        #pragma unroll
        for (int off = 16; off; off >>= 1)
            sum += __shfl_down_sync(0xffffffffu, sum, off);
        if (lane == 0) g_s[b * CIN + ci] = sum + mod_b[ci];
    }
}

// ---------------------------------------------------------------------------
// Stage 2: modulate, demodulate, and transpose weights to [b][tap][ci][co]
// ---------------------------------------------------------------------------
__global__ void k_wprep(const float* __restrict__ weight) {
    int co = blockIdx.x, b = blockIdx.y;
    __shared__ float vbuf[CIN * 9];
    __shared__ float red[256];
    const float scale = 1.0f / 48.0f;  // 1/sqrt(Cin*K*K) = 1/sqrt(2304)

    float part = 0.f;
    for (int idx = threadIdx.x; idx < CIN * 9; idx += 256) {
        int ci = idx / 9;
        float v = scale * weight[co * CIN * 9 + idx] * g_s[b * CIN + ci];
        vbuf[idx] = v;
        part += v * v;
    }
    red[threadIdx.x] = part;
    __syncthreads();
    for (int s = 128; s; s >>= 1) {
        if (threadIdx.x < s) red[threadIdx.x] += red[threadIdx.x + s];
        __syncthreads();
    }
    float demod = rsqrtf(red[0] + 1e-8f);
    for (int idx = threadIdx.x; idx < CIN * 9; idx += 256) {
        int ci = idx / 9, t = idx - ci * 9;
        g_w[((b * 9 + t) * CIN + ci) * COUT + co] = vbuf[idx] * demod;
    }
}

// ---------------------------------------------------------------------------
// Stage 3: transposed conv, phase-specialized.
//   out129[p,q] = sum_{y,x} X[y,x] * W[p-2y, q-2x],  0 <= taps <= 2
//   Phase (py,px): even dim -> 2 taps {ky=2,0} at y=m-1,m; odd dim -> 1 tap ky=1 at y=m.
// Block: 64 cout x 16x16 phase-grid tile, one batch. Thread: 8 cout x 8 cols.
// ---------------------------------------------------------------------------
template <int TY, int TX>
__global__ __launch_bounds__(256, 2)
void k_tconv(const float* __restrict__ x) {
    constexpr int GR = 64 + (TY == 2);
    constexpr int GC = 64 + (TX == 2);
    constexpr int tilesC = (GC + 15) / 16;
    constexpr int CC = 8;
    constexpr int XR = 16 + TY - 1;
    constexpr int XC = 16 + TX - 1;
    constexpr int XCP = 19;                 // odd pad width -> few bank conflicts
    constexpr int py = (TY == 2) ? 0 : 1;
    constexpr int px = (TX == 2) ? 0 : 1;
    constexpr int NT = TY * TX;

    int tile = blockIdx.x;
    int tr = tile / tilesC, tc = tile - tr * tilesC;
    int m0 = tr * 16, n0 = tc * 16;
    int cob = blockIdx.y * 64;
    int b = blockIdx.z;

    __shared__ float xs[CC][XR][XCP];
    __shared__ float ws[CC][NT][64];

    int tid = threadIdx.x;
    int cog = tid >> 5;          // 0..7 : cout group of 8
    int lane = tid & 31;
    int rrow = lane >> 1;        // 0..15 : phase-grid row within tile
    int cseg = lane & 1;         // 0..1  : col segment of 8

    float acc[8][8];
    #pragma unroll
    for (int j = 0; j < 8; j++)
        #pragma unroll
        for (int i = 0; i < 8; i++) acc[j][i] = 0.f;

    const int y0 = m0 - (TY - 1);
    const int xcol0 = n0 - (TX - 1);

    #pragma unroll 1
    for (int ci0 = 0; ci0 < CIN; ci0 += CC) {
        __syncthreads();
        // cooperative x tile load (zero-padded)
        for (int idx = tid; idx < CC * XR * XC; idx += 256) {
            int cc = idx / (XR * XC);
            int rem = idx - cc * (XR * XC);
            int r = rem / XC, c = rem - r * XC;
            int y = y0 + r, xx = xcol0 + c;
            float v = 0.f;
            if ((unsigned)y < 64u && (unsigned)xx < 64u)
                v = x[(((size_t)b * CIN + ci0 + cc) * HIN + y) * HIN + xx];
            xs[cc][r][c] = v;
        }
        // cooperative weight tile load (only this phase's taps)
        for (int idx = tid; idx < CC * NT * 64; idx += 256) {
            int col = idx & 63;
            int rem = idx >> 6;
            int t = rem % NT;
            int cc = rem / NT;
            int ry = t / TX, rx = t - ry * TX;
            int ky = (TY == 2) ? (2 - 2 * ry) : 1;
            int kx = (TX == 2) ? (2 - 2 * rx) : 1;
            ws[cc][t][col] =
                g_w[((b * 9 + ky * 3 + kx) * CIN + ci0 + cc) * COUT + cob + col];
        }
        __syncthreads();

        #pragma unroll
        for (int cc = 0; cc < CC; cc++) {
            #pragma unroll
            for (int ry = 0; ry < TY; ry++) {
                float xv[8 + TX - 1];
                #pragma unroll
                for (int i = 0; i < 8 + TX - 1; i++)
                    xv[i] = xs[cc][rrow + ry][cseg * 8 + i];
                #pragma unroll
                for (int rx = 0; rx < TX; rx++) {
                    const float4* wp =
                        reinterpret_cast<const float4*>(&ws[cc][ry * TX + rx][cog * 8]);
                    float4 wa = wp[0], wb = wp[1];
                    float w8[8] = {wa.x, wa.y, wa.z, wa.w, wb.x, wb.y, wb.z, wb.w};
                    #pragma unroll
                    for (int j = 0; j < 8; j++)
                        #pragma unroll
                        for (int i = 0; i < 8; i++)
                            acc[j][i] = fmaf(w8[j], xv[i + rx], acc[j][i]);
                }
            }
        }
    }

    // epilogue: scatter into the 129x129 grid at this phase's parity
    int m = m0 + rrow;
    if (m < GR) {
        int p = 2 * m + py;
        #pragma unroll
        for (int j = 0; j < 8; j++) {
            int co = cob + cog * 8 + j;
            float* op = g_o + (((size_t)b * COUT + co) * H129 + p) * H129;
            #pragma unroll
            for (int i = 0; i < 8; i++) {
                int n = n0 + cseg * 8 + i;
                if (n < GC) op[2 * n + px] = acc[j][i];
            }
        }
    }
}

// ---------------------------------------------------------------------------
// Stage 4: separable 4x4 blur (taps /4 each dim -> product /16 = bk1[t]bk1[s]*4/64)
//   blurred[u,v] = sum_{t,s} bk[t]bk[s] * o129[u+2-t, v+2-s], zero pad outside.
// ---------------------------------------------------------------------------
__global__ __launch_bounds__(256)
void k_blur(float* __restrict__ out) {
    int bc = blockIdx.x;           // b*COUT + co
    int u0 = blockIdx.y * 16;
    __shared__ float os[19][132];
    __shared__ float hs[19][132];
    const float bk[4] = {0.25f, 0.75f, 0.75f, 0.25f};
    const float* src = g_o + (size_t)bc * H129 * H129;

    for (int idx = threadIdx.x; idx < 19 * 132; idx += 256) {
        int r = idx / 132, c = idx - r * 132;
        int gr = u0 - 1 + r, gc = c - 1;
        float v = 0.f;
        if ((unsigned)gr < 129u && (unsigned)gc < 129u) v = src[gr * H129 + gc];
        os[r][c] = v;
    }
    __syncthreads();
    // horizontal: h[r][v] = sum_s bk[s]*o[r][v+2-s]  (os col offset +1)
    for (int idx = threadIdx.x; idx < 19 * 128; idx += 256) {
        int r = idx >> 7, v = idx & 127;
        float h = 0.f;
        #pragma unroll
        for (int s = 0; s < 4; s++) h += bk[s] * os[r][v + 3 - s];
        hs[r][v] = h;
    }
    __syncthreads();
    // vertical + store
    for (int idx = threadIdx.x; idx < 16 * 128; idx += 256) {
        int ul = idx >> 7, v = idx & 127;
        float o = 0.f;
        #pragma unroll
        for (int t = 0; t < 4; t++) o += bk[t] * hs[ul + 3 - t][v];
        out[((size_t)bc * HOUT + u0 + ul) * HOUT + v] = o;
    }
}

// ---------------------------------------------------------------------------
extern "C" void kernel_launch(void* const* d_in, const int* in_sizes, int n_in,
                              void* d_out, int out_size) {
    const float* x      = (const float*)d_in[0];
    const float* style  = (const float*)d_in[1];
    const float* weight = (const float*)d_in[2];
    const float* mod_w  = (const float*)d_in[3];
    const float* mod_b  = (const float*)d_in[4];
    float* out = (float*)d_out;

    k_style<<<B, 256>>>(style, mod_w, mod_b);
    k_wprep<<<dim3(COUT, B), 256>>>(weight);

    // phase (py,px): EE (2,2) grid 65x65, EO (2,1) 65x64, OE (1,2) 64x65, OO (1,1) 64x64
    k_tconv<2, 2><<<dim3(5 * 5, 2, B), 256>>>(x);
    k_tconv<2, 1><<<dim3(5 * 4, 2, B), 256>>>(x);
    k_tconv<1, 2><<<dim3(4 * 5, 2, B), 256>>>(x);
    k_tconv<1, 1><<<dim3(4 * 4, 2, B), 256>>>(x);

    k_blur<<<dim3(B * COUT, 8), 256>>>(out);
}

// round 3
// speedup vs baseline: 1.4365x; 1.4365x over previous
#include <cuda_runtime.h>

#define B    16
#define CIN  256
#define COUT 128
#define SDIM 512
#define HOUT 128
#define CC   8
#define PL   4420          // 65 * 68 padded plane
#define PSTR (4*PL)        // per-cout stride (4 phase planes)

// Scratch
__device__ float g_s[B * CIN];
__device__ float g_w[B * 9 * CIN * COUT];             // [b][tap ky*3+kx][ci][co]
__device__ float g_o[(size_t)B * COUT * 4 * PL];      // phase planes [b][co][ph][65][68]

typedef unsigned long long u64;

__device__ __forceinline__ unsigned su32(const void* p) {
    return (unsigned)__cvta_generic_to_shared(p);
}
__device__ __forceinline__ void cpa4(void* dst, const void* src, bool pred) {
    asm volatile("cp.async.ca.shared.global [%0],[%1],4,%2;\n"
                 :: "r"(su32(dst)), "l"(src), "r"(pred ? 4 : 0));
}
__device__ __forceinline__ void cpa16(void* dst, const void* src) {
    asm volatile("cp.async.ca.shared.global [%0],[%1],16;\n"
                 :: "r"(su32(dst)), "l"(src));
}
__device__ __forceinline__ void cp_commit() { asm volatile("cp.async.commit_group;"); }
__device__ __forceinline__ void cp_wait0()  { asm volatile("cp.async.wait_group 0;"); }

__device__ __forceinline__ u64 dup2(float v) {
    u64 r; asm("mov.b64 %0,{%1,%1};" : "=l"(r) : "f"(v)); return r;
}
__device__ __forceinline__ void fma2(u64& d, u64 a, u64 b) {
    asm("fma.rn.f32x2 %0,%1,%2,%0;" : "+l"(d) : "l"(a), "l"(b));
}
__device__ __forceinline__ float2 unpk(u64 v) {
    float2 f; asm("mov.b64 {%0,%1},%2;" : "=f"(f.x), "=f"(f.y) : "l"(v)); return f;
}

// ---------------------------------------------------------------------------
// Stage 1: s[b,ci] = style[b,:] . mod_w[ci,:] + mod_b[ci]
// ---------------------------------------------------------------------------
__global__ void k_style(const float* __restrict__ style,
                        const float* __restrict__ mod_w,
                        const float* __restrict__ mod_b) {
    int b = blockIdx.x;
    int warp = threadIdx.x >> 5, lane = threadIdx.x & 31;
    const float* st = style + b * SDIM;
    for (int ci = warp; ci < CIN; ci += 8) {
        const float* mw = mod_w + ci * SDIM;
        float sum = 0.f;
        for (int k = lane; k < SDIM; k += 32) sum += st[k] * mw[k];
        #pragma unroll
        for (int off = 16; off; off >>= 1)
            sum += __shfl_down_sync(0xffffffffu, sum, off);
        if (lane == 0) g_s[b * CIN + ci] = sum + mod_b[ci];
    }
}

// ---------------------------------------------------------------------------
// Stage 2: modulate + demodulate, transpose weights to [b][tap][ci][co]
// ---------------------------------------------------------------------------
__global__ void k_wprep(const float* __restrict__ weight) {
    int co = blockIdx.x, b = blockIdx.y;
    __shared__ float vbuf[CIN * 9];
    __shared__ float red[256];
    const float scale = 1.0f / 48.0f;

    float part = 0.f;
    for (int idx = threadIdx.x; idx < CIN * 9; idx += 256) {
        int ci = idx / 9;
        float v = scale * weight[co * CIN * 9 + idx] * g_s[b * CIN + ci];
        vbuf[idx] = v;
        part += v * v;
    }
    red[threadIdx.x] = part;
    __syncthreads();
    for (int s = 128; s; s >>= 1) {
        if (threadIdx.x < s) red[threadIdx.x] += red[threadIdx.x + s];
        __syncthreads();
    }
    float demod = rsqrtf(red[0] + 1e-8f);
    for (int idx = threadIdx.x; idx < CIN * 9; idx += 256) {
        int ci = idx / 9, t = idx - ci * 9;
        g_w[((b * 9 + t) * CIN + ci) * COUT + co] = vbuf[idx] * demod;
    }
}

// ---------------------------------------------------------------------------
// Stage 3: transposed conv, phase-specialized, 64x64 grid (border separate).
// Phase plane ph = py*2+px. FFMA2, cp.async double-buffered pipeline.
// ---------------------------------------------------------------------------
template <int TY, int TX>
__device__ __forceinline__ void tbody(
    const float* __restrict__ x,
    float (&xs)[2][CC][17][20], float (&ws)[2][CC][4][64],
    int b, int m0, int n0, int cob)
{
    constexpr int NT  = TY * TX;
    constexpr int XRa = 16 + TY - 1;
    constexpr int XCa = 16 + TX - 1;
    constexpr int PH  = ((TY == 2) ? 0 : 2) | ((TX == 2) ? 0 : 1);

    const int tid  = threadIdx.x;
    const int cog  = tid >> 5;
    const int lane = tid & 31;
    const int rrow = lane >> 1;
    const int cseg = lane & 1;
    const int y0   = m0 - (TY - 1);
    const int xc0  = n0 - (TX - 1);

    u64 acc[4][8];
    #pragma unroll
    for (int j = 0; j < 4; j++)
        #pragma unroll
        for (int i = 0; i < 8; i++) acc[j][i] = 0ull;

    auto issue = [&](int ci0, int buf) {
        const float* xb = x + ((size_t)b * CIN + ci0) * 4096;
        for (int idx = tid; idx < CC * XRa * XCa; idx += 256) {
            int cc  = idx / (XRa * XCa);
            int rem = idx - cc * (XRa * XCa);
            int r   = rem / XCa, c = rem - r * XCa;
            int y   = y0 + r, xx = xc0 + c;
            bool ok = ((unsigned)y < 64u) & ((unsigned)xx < 64u);
            cpa4(&xs[buf][cc][r][c], xb + cc * 4096 + (y & 63) * 64 + (xx & 63), ok);
        }
        for (int idx = tid; idx < CC * NT * 16; idx += 256) {
            int c4 = idx & 15;
            int t  = (idx >> 4) % NT;
            int cc = (idx >> 4) / NT;
            int ry = t / TX, rx = t - ry * TX;
            int ky = (TY == 2) ? (2 - 2 * ry) : 1;
            int kx = (TX == 2) ? (2 - 2 * rx) : 1;
            cpa16(&ws[buf][cc][t][c4 * 4],
                  g_w + (((size_t)b * 9 + ky * 3 + kx) * CIN + ci0 + cc) * COUT + cob + c4 * 4);
        }
    };

    issue(0, 0);
    cp_commit();
    int cur = 0;
    for (int c0 = 0; c0 < CIN / CC; c0++) {
        cp_wait0();
        __syncthreads();
        if (c0 + 1 < CIN / CC) { issue((c0 + 1) * CC, cur ^ 1); cp_commit(); }

        #pragma unroll 1
        for (int cc = 0; cc < CC; cc++) {
            #pragma unroll
            for (int ry = 0; ry < TY; ry++) {
                const float4* xp =
                    reinterpret_cast<const float4*>(&xs[cur][cc][rrow + ry][cseg * 8]);
                float4 q0 = xp[0], q1 = xp[1];
                u64 xx2[9];
                xx2[0] = dup2(q0.x); xx2[1] = dup2(q0.y);
                xx2[2] = dup2(q0.z); xx2[3] = dup2(q0.w);
                xx2[4] = dup2(q1.x); xx2[5] = dup2(q1.y);
                xx2[6] = dup2(q1.z); xx2[7] = dup2(q1.w);
                if (TX == 2) { float4 q2 = xp[2]; xx2[8] = dup2(q2.x); }
                #pragma unroll
                for (int rx = 0; rx < TX; rx++) {
                    const u64* wp =
                        reinterpret_cast<const u64*>(&ws[cur][cc][ry * TX + rx][cog * 8]);
                    u64 w0 = wp[0], w1 = wp[1], w2 = wp[2], w3 = wp[3];
                    #pragma unroll
                    for (int i = 0; i < 8; i++) {
                        fma2(acc[0][i], w0, xx2[i + rx]);
                        fma2(acc[1][i], w1, xx2[i + rx]);
                        fma2(acc[2][i], w2, xx2[i + rx]);
                        fma2(acc[3][i], w3, xx2[i + rx]);
                    }
                }
            }
        }
        cur ^= 1;
    }

    // epilogue: coalesced float4 stores into phase plane
    int m = m0 + rrow;
    size_t base = (size_t)(b * COUT + cob + cog * 8) * PSTR
                + (size_t)PH * PL + m * 68 + n0 + cseg * 8;
    #pragma unroll
    for (int j2 = 0; j2 < 4; j2++) {
        float lo[8], hi[8];
        #pragma unroll
        for (int i = 0; i < 8; i++) {
            float2 f = unpk(acc[j2][i]);
            lo[i] = f.x; hi[i] = f.y;
        }
        float* p0 = g_o + base + (size_t)(2 * j2) * PSTR;
        float* p1 = p0 + PSTR;
        *(float4*)(p0)     = make_float4(lo[0], lo[1], lo[2], lo[3]);
        *(float4*)(p0 + 4) = make_float4(lo[4], lo[5], lo[6], lo[7]);
        *(float4*)(p1)     = make_float4(hi[0], hi[1], hi[2], hi[3]);
        *(float4*)(p1 + 4) = make_float4(hi[4], hi[5], hi[6], hi[7]);
    }
}

__global__ __launch_bounds__(256, 2)
void k_tconv_all(const float* __restrict__ x) {
    __shared__ float xs[2][CC][17][20];
    __shared__ float ws[2][CC][4][64];
    int ph  = blockIdx.y >> 1;
    int cob = (blockIdx.y & 1) * 64;
    int b   = blockIdx.z;
    int m0  = (blockIdx.x >> 2) * 16;
    int n0  = (blockIdx.x & 3) * 16;
    switch (ph) {
        case 0:  tbody<2, 2>(x, xs, ws, b, m0, n0, cob); break;
        case 1:  tbody<2, 1>(x, xs, ws, b, m0, n0, cob); break;
        case 2:  tbody<1, 2>(x, xs, ws, b, m0, n0, cob); break;
        default: tbody<1, 1>(x, xs, ws, b, m0, n0, cob); break;
    }
}

// ---------------------------------------------------------------------------
// Stage 3b: border strips p=128 (side 0) and q=128 (side 1).
//   row p=128: q=2n  -> X[63,n-1]*W(2,2) + X[63,n]*W(2,0)
//              q=2n+1-> X[63,n]*W(2,1)
//   col q=128: p=2m  -> X[m-1,63]*W(2,2) + X[m,63]*W(0,2)   (p<128)
//              p=2m+1-> X[m,63]*W(1,2)
// ---------------------------------------------------------------------------
__global__ void k_border(const float* __restrict__ x) {
    int side = blockIdx.x & 1;
    int qt   = blockIdx.x >> 1;          // 0..16, q0 = qt*8
    int b    = blockIdx.y;
    int co   = threadIdx.x;              // 128 threads

    const float* W = g_w + (size_t)b * 9 * CIN * COUT;
    int tA = 8;                          // (2,2)
    int tB = side ? 2 : 6;               // (0,2) / (2,0)
    int tC = side ? 5 : 7;               // (1,2) / (2,1)

    float acc[8];
    #pragma unroll
    for (int k = 0; k < 8; k++) acc[k] = 0.f;

    for (int ci = 0; ci < CIN; ci++) {
        float wA = W[(tA * CIN + ci) * COUT + co];
        float wB = W[(tB * CIN + ci) * COUT + co];
        float wC = W[(tC * CIN + ci) * COUT + co];
        const float* xp = x + ((size_t)b * CIN + ci) * 4096;
        #pragma unroll
        for (int k = 0; k < 8; k++) {
            int q = qt * 8 + k;
            if (q > 128) continue;
            int n = q >> 1;
            if ((k & 1) == 0) {  // q even (qt*8 even)
                float xa = 0.f, xb = 0.f;
                if (n >= 1)  xa = side ? xp[(n - 1) * 64 + 63] : xp[63 * 64 + (n - 1)];
                if (n <= 63) xb = side ? xp[n * 64 + 63]       : xp[63 * 64 + n];
                acc[k] += wA * xa + wB * xb;
            } else {
                float xb = side ? xp[n * 64 + 63] : xp[63 * 64 + n];
                acc[k] += wC * xb;
            }
        }
    }

    size_t cb = (size_t)(b * COUT + co) * PSTR;
    #pragma unroll
    for (int k = 0; k < 8; k++) {
        int q = qt * 8 + k;
        if (q > 128) continue;
        if (side == 0) {
            int plane = q & 1;                         // (py=0, px=q&1)
            g_o[cb + (size_t)plane * PL + 64 * 68 + (q >> 1)] = acc[k];
        } else {
            if (q == 128) continue;                    // corner done by side 0
            int plane = (q & 1) * 2;                   // (py=q&1, px=0)
            g_o[cb + (size_t)plane * PL + (q >> 1) * 68 + 64] = acc[k];
        }
    }
}

// ---------------------------------------------------------------------------
// Stage 4: separable 4x4 blur, gathering from phase planes.
// ---------------------------------------------------------------------------
__global__ __launch_bounds__(256)
void k_blur(float* __restrict__ out) {
    int bc = blockIdx.x;
    int u0 = blockIdx.y * 16;
    __shared__ float os[19][132];
    __shared__ float hs[19][132];
    const float bk[4] = {0.25f, 0.75f, 0.75f, 0.25f};
    const float* src = g_o + (size_t)bc * PSTR;

    for (int idx = threadIdx.x; idx < 19 * 132; idx += 256) {
        int r = idx / 132, c = idx - r * 132;
        int gr = u0 - 1 + r, gc = c - 1;
        float v = 0.f;
        if ((unsigned)gr < 129u && (unsigned)gc < 129u) {
            int plane = ((gr & 1) << 1) | (gc & 1);
            v = src[(size_t)plane * PL + (gr >> 1) * 68 + (gc >> 1)];
        }
        os[r][c] = v;
    }
    __syncthreads();
    for (int idx = threadIdx.x; idx < 19 * 128; idx += 256) {
        int r = idx >> 7, v = idx & 127;
        float h = 0.f;
        #pragma unroll
        for (int s = 0; s < 4; s++) h += bk[s] * os[r][v + 3 - s];
        hs[r][v] = h;
    }
    __syncthreads();
    for (int idx = threadIdx.x; idx < 16 * 128; idx += 256) {
        int ul = idx >> 7, v = idx & 127;
        float o = 0.f;
        #pragma unroll
        for (int t = 0; t < 4; t++) o += bk[t] * hs[ul + 3 - t][v];
        out[((size_t)bc * HOUT + u0 + ul) * HOUT + v] = o;
    }
}

// ---------------------------------------------------------------------------
extern "C" void kernel_launch(void* const* d_in, const int* in_sizes, int n_in,
                              void* d_out, int out_size) {
    const float* x      = (const float*)d_in[0];
    const float* style  = (const float*)d_in[1];
    const float* weight = (const float*)d_in[2];
    const float* mod_w  = (const float*)d_in[3];
    const float* mod_b  = (const float*)d_in[4];
    float* out = (float*)d_out;

    k_style<<<B, 256>>>(style, mod_w, mod_b);
    k_wprep<<<dim3(COUT, B), 256>>>(weight);
    k_tconv_all<<<dim3(16, 8, B), 256>>>(x);
    k_border<<<dim3(34, B), 128>>>(x);
    k_blur<<<dim3(B * COUT, 8), 256>>>(out);
}

// round 4
// speedup vs baseline: 1.7146x; 1.1936x over previous
#include <cuda_runtime.h>

#define B    16
#define CIN  256
#define COUT 128
#define SDIM 512
#define HOUT 128
#define CC   8
#define PL   4420          // 65 * 68 padded plane
#define PSTR (4*PL)        // per-cout stride (4 phase planes)

// Scratch
__device__ float g_s[B * CIN];
__device__ float g_w[B * 9 * CIN * COUT];             // [b][tap ky*3+kx][ci][co]
__device__ float g_o[(size_t)B * COUT * 4 * PL];      // phase planes [b][co][ph][65][68]

typedef unsigned long long u64;

__device__ __forceinline__ unsigned su32(const void* p) {
    return (unsigned)__cvta_generic_to_shared(p);
}
__device__ __forceinline__ void cpa4(void* dst, const void* src, bool pred) {
    asm volatile("cp.async.ca.shared.global [%0],[%1],4,%2;\n"
                 :: "r"(su32(dst)), "l"(src), "r"(pred ? 4 : 0));
}
__device__ __forceinline__ void cpa16(void* dst, const void* src) {
    asm volatile("cp.async.ca.shared.global [%0],[%1],16;\n"
                 :: "r"(su32(dst)), "l"(src));
}
__device__ __forceinline__ void cp_commit() { asm volatile("cp.async.commit_group;"); }
__device__ __forceinline__ void cp_wait0()  { asm volatile("cp.async.wait_group 0;"); }

__device__ __forceinline__ u64 dup2(float v) {
    u64 r; asm("mov.b64 %0,{%1,%1};" : "=l"(r) : "f"(v)); return r;
}
__device__ __forceinline__ void fma2(u64& d, u64 a, u64 b) {
    asm("fma.rn.f32x2 %0,%1,%2,%0;" : "+l"(d) : "l"(a), "l"(b));
}
__device__ __forceinline__ float2 unpk(u64 v) {
    float2 f; asm("mov.b64 {%0,%1},%2;" : "=f"(f.x), "=f"(f.y) : "l"(v)); return f;
}

// ---------------------------------------------------------------------------
// Stage 1: s[b,ci] = style[b,:] . mod_w[ci,:] + mod_b[ci]
// ---------------------------------------------------------------------------
__global__ void k_style(const float* __restrict__ style,
                        const float* __restrict__ mod_w,
                        const float* __restrict__ mod_b) {
    int b = blockIdx.x;
    int warp = threadIdx.x >> 5, lane = threadIdx.x & 31;
    const float* st = style + b * SDIM;
    for (int ci = warp; ci < CIN; ci += 8) {
        const float* mw = mod_w + ci * SDIM;
        float sum = 0.f;
        for (int k = lane; k < SDIM; k += 32) sum += st[k] * mw[k];
        #pragma unroll
        for (int off = 16; off; off >>= 1)
            sum += __shfl_down_sync(0xffffffffu, sum, off);
        if (lane == 0) g_s[b * CIN + ci] = sum + mod_b[ci];
    }
}

// ---------------------------------------------------------------------------
// Stage 2: modulate + demodulate, transpose weights to [b][tap][ci][co]
// ---------------------------------------------------------------------------
__global__ void k_wprep(const float* __restrict__ weight) {
    int co = blockIdx.x, b = blockIdx.y;
    __shared__ float vbuf[CIN * 9];
    __shared__ float red[256];
    const float scale = 1.0f / 48.0f;

    float part = 0.f;
    for (int idx = threadIdx.x; idx < CIN * 9; idx += 256) {
        int ci = idx / 9;
        float v = scale * weight[co * CIN * 9 + idx] * g_s[b * CIN + ci];
        vbuf[idx] = v;
        part += v * v;
    }
    red[threadIdx.x] = part;
    __syncthreads();
    for (int s = 128; s; s >>= 1) {
        if (threadIdx.x < s) red[threadIdx.x] += red[threadIdx.x + s];
        __syncthreads();
    }
    float demod = rsqrtf(red[0] + 1e-8f);
    for (int idx = threadIdx.x; idx < CIN * 9; idx += 256) {
        int ci = idx / 9, t = idx - ci * 9;
        g_w[((b * 9 + t) * CIN + ci) * COUT + co] = vbuf[idx] * demod;
    }
}

// ---------------------------------------------------------------------------
// Stage 3: transposed conv, phase-specialized, 64x64 grid (border separate).
// ---------------------------------------------------------------------------
template <int TY, int TX>
__device__ __forceinline__ void tbody(
    const float* __restrict__ x,
    float (&xs)[2][CC][17][20], float (&ws)[2][CC][4][64],
    int b, int m0, int n0, int cob)
{
    constexpr int NT  = TY * TX;
    constexpr int XRa = 16 + TY - 1;
    constexpr int XCa = 16 + TX - 1;
    constexpr int PH  = ((TY == 2) ? 0 : 2) | ((TX == 2) ? 0 : 1);

    const int tid  = threadIdx.x;
    const int cog  = tid >> 5;
    const int lane = tid & 31;
    const int rrow = lane >> 1;
    const int cseg = lane & 1;
    const int y0   = m0 - (TY - 1);
    const int xc0  = n0 - (TX - 1);

    u64 acc[4][8];
    #pragma unroll
    for (int j = 0; j < 4; j++)
        #pragma unroll
        for (int i = 0; i < 8; i++) acc[j][i] = 0ull;

    auto issue = [&](int ci0, int buf) {
        const float* xb = x + ((size_t)b * CIN + ci0) * 4096;
        for (int idx = tid; idx < CC * XRa * XCa; idx += 256) {
            int cc  = idx / (XRa * XCa);
            int rem = idx - cc * (XRa * XCa);
            int r   = rem / XCa, c = rem - r * XCa;
            int y   = y0 + r, xx = xc0 + c;
            bool ok = ((unsigned)y < 64u) & ((unsigned)xx < 64u);
            cpa4(&xs[buf][cc][r][c], xb + cc * 4096 + (y & 63) * 64 + (xx & 63), ok);
        }
        for (int idx = tid; idx < CC * NT * 16; idx += 256) {
            int c4 = idx & 15;
            int t  = (idx >> 4) % NT;
            int cc = (idx >> 4) / NT;
            int ry = t / TX, rx = t - ry * TX;
            int ky = (TY == 2) ? (2 - 2 * ry) : 1;
            int kx = (TX == 2) ? (2 - 2 * rx) : 1;
            cpa16(&ws[buf][cc][t][c4 * 4],
                  g_w + (((size_t)b * 9 + ky * 3 + kx) * CIN + ci0 + cc) * COUT + cob + c4 * 4);
        }
    };

    issue(0, 0);
    cp_commit();
    int cur = 0;
    for (int c0 = 0; c0 < CIN / CC; c0++) {
        cp_wait0();
        __syncthreads();
        if (c0 + 1 < CIN / CC) { issue((c0 + 1) * CC, cur ^ 1); cp_commit(); }

        #pragma unroll 1
        for (int cc = 0; cc < CC; cc++) {
            #pragma unroll
            for (int ry = 0; ry < TY; ry++) {
                const float4* xp =
                    reinterpret_cast<const float4*>(&xs[cur][cc][rrow + ry][cseg * 8]);
                float4 q0 = xp[0], q1 = xp[1];
                u64 xx2[9];
                xx2[0] = dup2(q0.x); xx2[1] = dup2(q0.y);
                xx2[2] = dup2(q0.z); xx2[3] = dup2(q0.w);
                xx2[4] = dup2(q1.x); xx2[5] = dup2(q1.y);
                xx2[6] = dup2(q1.z); xx2[7] = dup2(q1.w);
                if (TX == 2) { float4 q2 = xp[2]; xx2[8] = dup2(q2.x); }
                #pragma unroll
                for (int rx = 0; rx < TX; rx++) {
                    const u64* wp =
                        reinterpret_cast<const u64*>(&ws[cur][cc][ry * TX + rx][cog * 8]);
                    u64 w0 = wp[0], w1 = wp[1], w2 = wp[2], w3 = wp[3];
                    #pragma unroll
                    for (int i = 0; i < 8; i++) {
                        fma2(acc[0][i], w0, xx2[i + rx]);
                        fma2(acc[1][i], w1, xx2[i + rx]);
                        fma2(acc[2][i], w2, xx2[i + rx]);
                        fma2(acc[3][i], w3, xx2[i + rx]);
                    }
                }
            }
        }
        cur ^= 1;
    }

    int m = m0 + rrow;
    size_t base = (size_t)(b * COUT + cob + cog * 8) * PSTR
                + (size_t)PH * PL + m * 68 + n0 + cseg * 8;
    #pragma unroll
    for (int j2 = 0; j2 < 4; j2++) {
        float lo[8], hi[8];
        #pragma unroll
        for (int i = 0; i < 8; i++) {
            float2 f = unpk(acc[j2][i]);
            lo[i] = f.x; hi[i] = f.y;
        }
        float* p0 = g_o + base + (size_t)(2 * j2) * PSTR;
        float* p1 = p0 + PSTR;
        *(float4*)(p0)     = make_float4(lo[0], lo[1], lo[2], lo[3]);
        *(float4*)(p0 + 4) = make_float4(lo[4], lo[5], lo[6], lo[7]);
        *(float4*)(p1)     = make_float4(hi[0], hi[1], hi[2], hi[3]);
        *(float4*)(p1 + 4) = make_float4(hi[4], hi[5], hi[6], hi[7]);
    }
}

__global__ __launch_bounds__(256, 2)
void k_tconv_all(const float* __restrict__ x) {
    __shared__ float xs[2][CC][17][20];
    __shared__ float ws[2][CC][4][64];
    int ph  = blockIdx.y >> 1;
    int cob = (blockIdx.y & 1) * 64;
    int b   = blockIdx.z;
    int m0  = (blockIdx.x >> 2) * 16;
    int n0  = (blockIdx.x & 3) * 16;
    switch (ph) {
        case 0:  tbody<2, 2>(x, xs, ws, b, m0, n0, cob); break;
        case 1:  tbody<2, 1>(x, xs, ws, b, m0, n0, cob); break;
        case 2:  tbody<1, 2>(x, xs, ws, b, m0, n0, cob); break;
        default: tbody<1, 1>(x, xs, ws, b, m0, n0, cob); break;
    }
}

// ---------------------------------------------------------------------------
// Stage 3b (v2): border strips p=128 (side 0) and q=128 (side 1), smem-staged.
//   row p=128: q=2n  -> xr[n-1]*W(2,2) + xr[n]*W(2,0);  q=2n+1 -> xr[n]*W(2,1)
//   col q=128: p=2m  -> xc[m-1]*W(2,2) + xc[m]*W(0,2);  p=2m+1 -> xc[m]*W(1,2)
//   xr[n] = x[b,ci,63,n], xc[m] = x[b,ci,m,63]
// Block: (b, side, cout-half of 64). Threads: 256 = 64 co x 4 q-segments.
// ---------------------------------------------------------------------------
__global__ __launch_bounds__(256)
void k_border(const float* __restrict__ x) {
    int blk  = blockIdx.x;
    int cog  = blk & 1;           // cout half
    int side = (blk >> 1) & 1;
    int b    = blk >> 2;

    __shared__ float xsb[CC][66];     // xsb[cc][0]=0, [1+n]=border val, [65]=0
    __shared__ float wsb[3][CC][64];  // taps A,B,C

    const int tid  = threadIdx.x;
    const int co_l = tid & 63;
    const int qs   = tid >> 6;        // 0..3
    const int q0   = qs * 33;
    const int co   = cog * 64 + co_l;

    const int tA = 8;                      // (2,2)
    const int tB = side ? 2 : 6;           // (0,2) / (2,0)
    const int tC = side ? 5 : 7;           // (1,2) / (2,1)
    const float* W = g_w + (size_t)b * 9 * CIN * COUT;
    const float* xb = x + (size_t)b * CIN * 4096;

    float acc[33];
    #pragma unroll
    for (int k = 0; k < 33; k++) acc[k] = 0.f;

    for (int ci0 = 0; ci0 < CIN; ci0 += CC) {
        __syncthreads();
        // stage x border rows: 8 cc x 64 values (+ zero pads)
        for (int idx = tid; idx < CC * 64; idx += 256) {
            int cc = idx >> 6, n = idx & 63;
            const float* xp = xb + (size_t)(ci0 + cc) * 4096;
            xsb[cc][1 + n] = side ? xp[n * 64 + 63] : xp[63 * 64 + n];
        }
        if (tid < 2 * CC) {
            int cc = tid >> 1;
            xsb[cc][(tid & 1) ? 65 : 0] = 0.f;
        }
        // stage weights: 3 taps x 8 cc x 64 co
        for (int idx = tid; idx < 3 * CC * 64; idx += 256) {
            int c = idx & 63;
            int cc = (idx >> 6) & 7;
            int t3 = idx >> 9;
            int tap = (t3 == 0) ? tA : (t3 == 1) ? tB : tC;
            wsb[t3][cc][c] = W[((size_t)tap * CIN + ci0 + cc) * COUT + co - co_l + c];
        }
        __syncthreads();

        #pragma unroll
        for (int cc = 0; cc < CC; cc++) {
            float wA = wsb[0][cc][co_l];
            float wB = wsb[1][cc][co_l];
            float wC = wsb[2][cc][co_l];
            #pragma unroll
            for (int k = 0; k < 33; k++) {
                int q = q0 + k;
                if (q > 128) break;
                int n = q >> 1;
                if ((q & 1) == 0) {
                    acc[k] = fmaf(wA, xsb[cc][n], fmaf(wB, xsb[cc][n + 1], acc[k]));
                } else {
                    acc[k] = fmaf(wC, xsb[cc][n + 1], acc[k]);
                }
            }
        }
    }

    size_t cb = (size_t)(b * COUT + co) * PSTR;
    #pragma unroll
    for (int k = 0; k < 33; k++) {
        int q = q0 + k;
        if (q > 128) break;
        if (side == 0) {
            int plane = q & 1;
            g_o[cb + (size_t)plane * PL + 64 * 68 + (q >> 1)] = acc[k];
        } else {
            if (q == 128) continue;       // corner written by side 0
            int plane = (q & 1) * 2;
            g_o[cb + (size_t)plane * PL + (q >> 1) * 68 + 64] = acc[k];
        }
    }
}

// ---------------------------------------------------------------------------
// Stage 4: separable 4x4 blur, gathering from phase planes.
// ---------------------------------------------------------------------------
__global__ __launch_bounds__(256)
void k_blur(float* __restrict__ out) {
    int bc = blockIdx.x;
    int u0 = blockIdx.y * 16;
    __shared__ float os[19][132];
    __shared__ float hs[19][132];
    const float bk[4] = {0.25f, 0.75f, 0.75f, 0.25f};
    const float* src = g_o + (size_t)bc * PSTR;

    for (int idx = threadIdx.x; idx < 19 * 132; idx += 256) {
        int r = idx / 132, c = idx - r * 132;
        int gr = u0 - 1 + r, gc = c - 1;
        float v = 0.f;
        if ((unsigned)gr < 129u && (unsigned)gc < 129u) {
            int plane = ((gr & 1) << 1) | (gc & 1);
            v = src[(size_t)plane * PL + (gr >> 1) * 68 + (gc >> 1)];
        }
        os[r][c] = v;
    }
    __syncthreads();
    for (int idx = threadIdx.x; idx < 19 * 128; idx += 256) {
        int r = idx >> 7, v = idx & 127;
        float h = 0.f;
        #pragma unroll
        for (int s = 0; s < 4; s++) h += bk[s] * os[r][v + 3 - s];
        hs[r][v] = h;
    }
    __syncthreads();
    for (int idx = threadIdx.x; idx < 16 * 128; idx += 256) {
        int ul = idx >> 7, v = idx & 127;
        float o = 0.f;
        #pragma unroll
        for (int t = 0; t < 4; t++) o += bk[t] * hs[ul + 3 - t][v];
        out[((size_t)bc * HOUT + u0 + ul) * HOUT + v] = o;
    }
}

// ---------------------------------------------------------------------------
extern "C" void kernel_launch(void* const* d_in, const int* in_sizes, int n_in,
                              void* d_out, int out_size) {
    const float* x      = (const float*)d_in[0];
    const float* style  = (const float*)d_in[1];
    const float* weight = (const float*)d_in[2];
    const float* mod_w  = (const float*)d_in[3];
    const float* mod_b  = (const float*)d_in[4];
    float* out = (float*)d_out;

    k_style<<<B, 256>>>(style, mod_w, mod_b);
    k_wprep<<<dim3(COUT, B), 256>>>(weight);
    k_tconv_all<<<dim3(16, 8, B), 256>>>(x);
    k_border<<<dim3(B * 4), 256>>>(x);
    k_blur<<<dim3(B * COUT, 8), 256>>>(out);
}

// round 5
// speedup vs baseline: 1.9442x; 1.1339x over previous
#include <cuda_runtime.h>

#define B    16
#define CIN  256
#define COUT 128
#define SDIM 512
#define HOUT 128
#define CC   8
#define PL   4420          // 65 * 68 padded plane
#define PSTR (4*PL)        // per-cout stride (4 phase planes)
#define NSPL 8             // border ci-splits

// Scratch
__device__ float g_s[B * CIN];
__device__ float g_w[B * 9 * CIN * COUT];             // [b][tap ky*3+kx][ci][co]
__device__ float g_o[(size_t)B * COUT * 4 * PL];      // phase planes [b][co][ph][65][68]

typedef unsigned long long u64;

__device__ __forceinline__ unsigned su32(const void* p) {
    return (unsigned)__cvta_generic_to_shared(p);
}
__device__ __forceinline__ void cpa4(void* dst, const void* src, bool pred) {
    asm volatile("cp.async.ca.shared.global [%0],[%1],4,%2;\n"
                 :: "r"(su32(dst)), "l"(src), "r"(pred ? 4 : 0));
}
__device__ __forceinline__ void cpa16(void* dst, const void* src) {
    asm volatile("cp.async.ca.shared.global [%0],[%1],16;\n"
                 :: "r"(su32(dst)), "l"(src));
}
__device__ __forceinline__ void cp_commit() { asm volatile("cp.async.commit_group;"); }
__device__ __forceinline__ void cp_wait0()  { asm volatile("cp.async.wait_group 0;"); }

__device__ __forceinline__ u64 dup2(float v) {
    u64 r; asm("mov.b64 %0,{%1,%1};" : "=l"(r) : "f"(v)); return r;
}
__device__ __forceinline__ void fma2(u64& d, u64 a, u64 b) {
    asm("fma.rn.f32x2 %0,%1,%2,%0;" : "+l"(d) : "l"(a), "l"(b));
}
__device__ __forceinline__ float2 unpk(u64 v) {
    float2 f; asm("mov.b64 {%0,%1},%2;" : "=f"(f.x), "=f"(f.y) : "l"(v)); return f;
}

// ---------------------------------------------------------------------------
// Stage 1: s[b,ci] = style[b,:] . mod_w[ci,:] + mod_b[ci]
// ---------------------------------------------------------------------------
__global__ void k_style(const float* __restrict__ style,
                        const float* __restrict__ mod_w,
                        const float* __restrict__ mod_b) {
    int b = blockIdx.x;
    int warp = threadIdx.x >> 5, lane = threadIdx.x & 31;
    const float* st = style + b * SDIM;
    for (int ci = warp; ci < CIN; ci += 8) {
        const float* mw = mod_w + ci * SDIM;
        float sum = 0.f;
        for (int k = lane; k < SDIM; k += 32) sum += st[k] * mw[k];
        #pragma unroll
        for (int off = 16; off; off >>= 1)
            sum += __shfl_down_sync(0xffffffffu, sum, off);
        if (lane == 0) g_s[b * CIN + ci] = sum + mod_b[ci];
    }
}

// ---------------------------------------------------------------------------
// Stage 2: modulate + demodulate, transpose weights to [b][tap][ci][co].
// Also zero-inits this (b,co)'s border cells in g_o (written by k_border adds).
// ---------------------------------------------------------------------------
__global__ void k_wprep(const float* __restrict__ weight) {
    int co = blockIdx.x, b = blockIdx.y;
    __shared__ float vbuf[CIN * 9];
    __shared__ float red[256];
    const float scale = 1.0f / 48.0f;

    // zero border cells: plane0 row64 [0..64], plane1 row64 [0..63],
    // plane0 col64 rows[0..63], plane2 col64 rows[0..63]
    {
        float* base = g_o + (size_t)(b * COUT + co) * PSTR;
        int t = threadIdx.x;
        if (t < 65)       base[0 * PL + 64 * 68 + t] = 0.f;
        else if (t < 129) base[1 * PL + 64 * 68 + (t - 65)] = 0.f;
        else if (t < 193) base[0 * PL + (t - 129) * 68 + 64] = 0.f;
        else              base[2 * PL + (t - 193) * 68 + 64] = 0.f;  // t<257 handled below
        if (threadIdx.x == 255) base[2 * PL + 63 * 68 + 64] = 0.f;   // cover row 63 (t 193..255 = 63 rows)
    }

    float part = 0.f;
    for (int idx = threadIdx.x; idx < CIN * 9; idx += 256) {
        int ci = idx / 9;
        float v = scale * weight[co * CIN * 9 + idx] * g_s[b * CIN + ci];
        vbuf[idx] = v;
        part += v * v;
    }
    red[threadIdx.x] = part;
    __syncthreads();
    for (int s = 128; s; s >>= 1) {
        if (threadIdx.x < s) red[threadIdx.x] += red[threadIdx.x + s];
        __syncthreads();
    }
    float demod = rsqrtf(red[0] + 1e-8f);
    for (int idx = threadIdx.x; idx < CIN * 9; idx += 256) {
        int ci = idx / 9, t = idx - ci * 9;
        g_w[((b * 9 + t) * CIN + ci) * COUT + co] = vbuf[idx] * demod;
    }
}

// ---------------------------------------------------------------------------
// Stage 3: transposed conv, phase-specialized, 64x64 grid (border separate).
// ---------------------------------------------------------------------------
template <int TY, int TX>
__device__ __forceinline__ void tbody(
    const float* __restrict__ x,
    float (&xs)[2][CC][17][20], float (&ws)[2][CC][4][64],
    int b, int m0, int n0, int cob)
{
    constexpr int NT  = TY * TX;
    constexpr int XRa = 16 + TY - 1;
    constexpr int XCa = 16 + TX - 1;
    constexpr int PH  = ((TY == 2) ? 0 : 2) | ((TX == 2) ? 0 : 1);

    const int tid  = threadIdx.x;
    const int cog  = tid >> 5;
    const int lane = tid & 31;
    const int rrow = lane >> 1;
    const int cseg = lane & 1;
    const int y0   = m0 - (TY - 1);
    const int xc0  = n0 - (TX - 1);

    u64 acc[4][8];
    #pragma unroll
    for (int j = 0; j < 4; j++)
        #pragma unroll
        for (int i = 0; i < 8; i++) acc[j][i] = 0ull;

    auto issue = [&](int ci0, int buf) {
        const float* xb = x + ((size_t)b * CIN + ci0) * 4096;
        for (int idx = tid; idx < CC * XRa * XCa; idx += 256) {
            int cc  = idx / (XRa * XCa);
            int rem = idx - cc * (XRa * XCa);
            int r   = rem / XCa, c = rem - r * XCa;
            int y   = y0 + r, xx = xc0 + c;
            bool ok = ((unsigned)y < 64u) & ((unsigned)xx < 64u);
            cpa4(&xs[buf][cc][r][c], xb + cc * 4096 + (y & 63) * 64 + (xx & 63), ok);
        }
        for (int idx = tid; idx < CC * NT * 16; idx += 256) {
            int c4 = idx & 15;
            int t  = (idx >> 4) % NT;
            int cc = (idx >> 4) / NT;
            int ry = t / TX, rx = t - ry * TX;
            int ky = (TY == 2) ? (2 - 2 * ry) : 1;
            int kx = (TX == 2) ? (2 - 2 * rx) : 1;
            cpa16(&ws[buf][cc][t][c4 * 4],
                  g_w + (((size_t)b * 9 + ky * 3 + kx) * CIN + ci0 + cc) * COUT + cob + c4 * 4);
        }
    };

    issue(0, 0);
    cp_commit();
    int cur = 0;
    for (int c0 = 0; c0 < CIN / CC; c0++) {
        cp_wait0();
        __syncthreads();
        if (c0 + 1 < CIN / CC) { issue((c0 + 1) * CC, cur ^ 1); cp_commit(); }

        #pragma unroll 1
        for (int cc = 0; cc < CC; cc++) {
            #pragma unroll
            for (int ry = 0; ry < TY; ry++) {
                const float4* xp =
                    reinterpret_cast<const float4*>(&xs[cur][cc][rrow + ry][cseg * 8]);
                float4 q0 = xp[0], q1 = xp[1];
                u64 xx2[9];
                xx2[0] = dup2(q0.x); xx2[1] = dup2(q0.y);
                xx2[2] = dup2(q0.z); xx2[3] = dup2(q0.w);
                xx2[4] = dup2(q1.x); xx2[5] = dup2(q1.y);
                xx2[6] = dup2(q1.z); xx2[7] = dup2(q1.w);
                if (TX == 2) { float4 q2 = xp[2]; xx2[8] = dup2(q2.x); }
                #pragma unroll
                for (int rx = 0; rx < TX; rx++) {
                    const u64* wp =
                        reinterpret_cast<const u64*>(&ws[cur][cc][ry * TX + rx][cog * 8]);
                    u64 w0 = wp[0], w1 = wp[1], w2 = wp[2], w3 = wp[3];
                    #pragma unroll
                    for (int i = 0; i < 8; i++) {
                        fma2(acc[0][i], w0, xx2[i + rx]);
                        fma2(acc[1][i], w1, xx2[i + rx]);
                        fma2(acc[2][i], w2, xx2[i + rx]);
                        fma2(acc[3][i], w3, xx2[i + rx]);
                    }
                }
            }
        }
        cur ^= 1;
    }

    int m = m0 + rrow;
    size_t base = (size_t)(b * COUT + cob + cog * 8) * PSTR
                + (size_t)PH * PL + m * 68 + n0 + cseg * 8;
    #pragma unroll
    for (int j2 = 0; j2 < 4; j2++) {
        float lo[8], hi[8];
        #pragma unroll
        for (int i = 0; i < 8; i++) {
            float2 f = unpk(acc[j2][i]);
            lo[i] = f.x; hi[i] = f.y;
        }
        float* p0 = g_o + base + (size_t)(2 * j2) * PSTR;
        float* p1 = p0 + PSTR;
        *(float4*)(p0)     = make_float4(lo[0], lo[1], lo[2], lo[3]);
        *(float4*)(p0 + 4) = make_float4(lo[4], lo[5], lo[6], lo[7]);
        *(float4*)(p1)     = make_float4(hi[0], hi[1], hi[2], hi[3]);
        *(float4*)(p1 + 4) = make_float4(hi[4], hi[5], hi[6], hi[7]);
    }
}

__global__ __launch_bounds__(256, 2)
void k_tconv_all(const float* __restrict__ x) {
    __shared__ float xs[2][CC][17][20];
    __shared__ float ws[2][CC][4][64];
    int ph  = blockIdx.y >> 1;
    int cob = (blockIdx.y & 1) * 64;
    int b   = blockIdx.z;
    int m0  = (blockIdx.x >> 2) * 16;
    int n0  = (blockIdx.x & 3) * 16;
    switch (ph) {
        case 0:  tbody<2, 2>(x, xs, ws, b, m0, n0, cob); break;
        case 1:  tbody<2, 1>(x, xs, ws, b, m0, n0, cob); break;
        case 2:  tbody<1, 2>(x, xs, ws, b, m0, n0, cob); break;
        default: tbody<1, 1>(x, xs, ws, b, m0, n0, cob); break;
    }
}

// ---------------------------------------------------------------------------
// Stage 3b (v3): border strips, ci-split x8, cp.async pipelined, atomicAdd.
//   row p=128: q=2n  -> xr[n-1]*W(2,2) + xr[n]*W(2,0);  q=2n+1 -> xr[n]*W(2,1)
//   col q=128: p=2m  -> xc[m-1]*W(2,2) + xc[m]*W(0,2);  p=2m+1 -> xc[m]*W(1,2)
// Block: (b, side, cout-half, ci-split). Threads: 256 = 64 co x 4 q-segments.
// ---------------------------------------------------------------------------
__global__ __launch_bounds__(256)
void k_border(const float* __restrict__ x) {
    int blk   = blockIdx.x;
    int split = blk & (NSPL - 1);
    int cog   = (blk >> 3) & 1;
    int side  = (blk >> 4) & 1;
    int b     = blk >> 5;

    __shared__ float xsb[2][CC][66];
    __shared__ float wsb[2][3][CC][64];

    const int tid  = threadIdx.x;
    const int co_l = tid & 63;
    const int qs   = tid >> 6;
    const int q0   = qs * 33;
    const int co   = cog * 64 + co_l;

    const int tA = 8;
    const int tB = side ? 2 : 6;
    const int tC = side ? 5 : 7;
    const float* W  = g_w + (size_t)b * 9 * CIN * COUT;
    const float* xb = x + (size_t)b * CIN * 4096;
    const int ci_base = split * (CIN / NSPL);   // 32 ci per split

    // zero pads (constant across chunks, both buffers)
    if (tid < 4 * CC) {
        int buf = tid & 1, cc = (tid >> 2);
        xsb[buf][cc & 7][((tid >> 1) & 1) ? 65 : 0] = 0.f;
    }
    __syncthreads();

    auto issue = [&](int ci0, int buf) {
        for (int idx = tid; idx < CC * 64; idx += 256) {
            int cc = idx >> 6, n = idx & 63;
            const float* xp = xb + (size_t)(ci0 + cc) * 4096;
            cpa4(&xsb[buf][cc][1 + n], side ? (xp + n * 64 + 63) : (xp + 63 * 64 + n), true);
        }
        for (int idx = tid; idx < 3 * CC * 16; idx += 256) {
            int c4 = idx & 15;
            int cc = (idx >> 4) & 7;
            int t3 = idx >> 7;
            int tap = (t3 == 0) ? tA : (t3 == 1) ? tB : tC;
            cpa16(&wsb[buf][t3][cc][c4 * 4],
                  W + ((size_t)tap * CIN + ci0 + cc) * COUT + cog * 64 + c4 * 4);
        }
    };

    float acc[33];
    #pragma unroll
    for (int k = 0; k < 33; k++) acc[k] = 0.f;

    issue(ci_base, 0);
    cp_commit();
    int cur = 0;
    constexpr int NCH = (CIN / NSPL) / CC;   // 4
    for (int c0 = 0; c0 < NCH; c0++) {
        cp_wait0();
        __syncthreads();
        if (c0 + 1 < NCH) { issue(ci_base + (c0 + 1) * CC, cur ^ 1); cp_commit(); }

        #pragma unroll
        for (int cc = 0; cc < CC; cc++) {
            float wA = wsb[cur][0][cc][co_l];
            float wB = wsb[cur][1][cc][co_l];
            float wC = wsb[cur][2][cc][co_l];
            #pragma unroll
            for (int k = 0; k < 33; k++) {
                int q = q0 + k;
                int n = q >> 1;
                if (q <= 128) {
                    if ((q & 1) == 0)
                        acc[k] = fmaf(wA, xsb[cur][cc][n], fmaf(wB, xsb[cur][cc][n + 1], acc[k]));
                    else
                        acc[k] = fmaf(wC, xsb[cur][cc][n + 1], acc[k]);
                }
            }
        }
        __syncthreads();
        cur ^= 1;
    }

    size_t cb = (size_t)(b * COUT + co) * PSTR;
    #pragma unroll
    for (int k = 0; k < 33; k++) {
        int q = q0 + k;
        if (q > 128) continue;
        if (side == 0) {
            int plane = q & 1;
            atomicAdd(&g_o[cb + (size_t)plane * PL + 64 * 68 + (q >> 1)], acc[k]);
        } else {
            if (q == 128) continue;
            int plane = (q & 1) * 2;
            atomicAdd(&g_o[cb + (size_t)plane * PL + (q >> 1) * 68 + 64], acc[k]);
        }
    }
}

// ---------------------------------------------------------------------------
// Stage 4: separable 4x4 blur, gathering from phase planes.
// ---------------------------------------------------------------------------
__global__ __launch_bounds__(256)
void k_blur(float* __restrict__ out) {
    int bc = blockIdx.x;
    int u0 = blockIdx.y * 16;
    __shared__ float os[19][132];
    __shared__ float hs[19][132];
    const float bk[4] = {0.25f, 0.75f, 0.75f, 0.25f};
    const float* src = g_o + (size_t)bc * PSTR;

    for (int idx = threadIdx.x; idx < 19 * 132; idx += 256) {
        int r = idx / 132, c = idx - r * 132;
        int gr = u0 - 1 + r, gc = c - 1;
        float v = 0.f;
        if ((unsigned)gr < 129u && (unsigned)gc < 129u) {
            int plane = ((gr & 1) << 1) | (gc & 1);
            v = src[(size_t)plane * PL + (gr >> 1) * 68 + (gc >> 1)];
        }
        os[r][c] = v;
    }
    __syncthreads();
    for (int idx = threadIdx.x; idx < 19 * 128; idx += 256) {
        int r = idx >> 7, v = idx & 127;
        float h = 0.f;
        #pragma unroll
        for (int s = 0; s < 4; s++) h += bk[s] * os[r][v + 3 - s];
        hs[r][v] = h;
    }
    __syncthreads();
    for (int idx = threadIdx.x; idx < 16 * 128; idx += 256) {
        int ul = idx >> 7, v = idx & 127;
        float o = 0.f;
        #pragma unroll
        for (int t = 0; t < 4; t++) o += bk[t] * hs[ul + 3 - t][v];
        out[((size_t)bc * HOUT + u0 + ul) * HOUT + v] = o;
    }
}

// ---------------------------------------------------------------------------
extern "C" void kernel_launch(void* const* d_in, const int* in_sizes, int n_in,
                              void* d_out, int out_size) {
    const float* x      = (const float*)d_in[0];
    const float* style  = (const float*)d_in[1];
    const float* weight = (const float*)d_in[2];
    const float* mod_w  = (const float*)d_in[3];
    const float* mod_b  = (const float*)d_in[4];
    float* out = (float*)d_out;

    k_style<<<B, 256>>>(style, mod_w, mod_b);
    k_wprep<<<dim3(COUT, B), 256>>>(weight);
    k_tconv_all<<<dim3(16, 8, B), 256>>>(x);
    k_border<<<dim3(B * 4 * NSPL), 256>>>(x);
    k_blur<<<dim3(B * COUT, 8), 256>>>(out);
}

// round 6
// speedup vs baseline: 1.9449x; 1.0004x over previous
#include <cuda_runtime.h>

#define B    16
#define CIN  256
#define COUT 128
#define SDIM 512
#define HOUT 128
#define CC   8
#define PL   4420          // 65 * 68 padded plane
#define PSTR (4*PL)        // per-cout stride (4 phase planes)
#define NSPL 8             // border ci-splits

// Scratch
__device__ float g_s[B * CIN];
__device__ float g_w[B * 9 * CIN * COUT];             // [b][tap ky*3+kx][ci][co]
__device__ float g_o[(size_t)B * COUT * 4 * PL];      // phase planes [b][co][ph][65][68]

typedef unsigned long long u64;

__device__ __forceinline__ unsigned su32(const void* p) {
    return (unsigned)__cvta_generic_to_shared(p);
}
__device__ __forceinline__ void cpa4(void* dst, const void* src, bool pred) {
    asm volatile("cp.async.ca.shared.global [%0],[%1],4,%2;\n"
                 :: "r"(su32(dst)), "l"(src), "r"(pred ? 4 : 0));
}
__device__ __forceinline__ void cpa16(void* dst, const void* src) {
    asm volatile("cp.async.ca.shared.global [%0],[%1],16;\n"
                 :: "r"(su32(dst)), "l"(src));
}
__device__ __forceinline__ void cp_commit() { asm volatile("cp.async.commit_group;"); }
__device__ __forceinline__ void cp_wait0()  { asm volatile("cp.async.wait_group 0;"); }

__device__ __forceinline__ u64 dup2(float v) {
    u64 r; asm("mov.b64 %0,{%1,%1};" : "=l"(r) : "f"(v)); return r;
}
__device__ __forceinline__ void fma2(u64& d, u64 a, u64 b) {
    asm("fma.rn.f32x2 %0,%1,%2,%0;" : "+l"(d) : "l"(a), "l"(b));
}
__device__ __forceinline__ float2 unpk(u64 v) {
    float2 f; asm("mov.b64 {%0,%1},%2;" : "=f"(f.x), "=f"(f.y) : "l"(v)); return f;
}

// ---------------------------------------------------------------------------
// Stage 1: s[b,ci] = style[b,:] . mod_w[ci,:] + mod_b[ci]
// ---------------------------------------------------------------------------
__global__ void k_style(const float* __restrict__ style,
                        const float* __restrict__ mod_w,
                        const float* __restrict__ mod_b) {
    int b = blockIdx.x;
    int warp = threadIdx.x >> 5, lane = threadIdx.x & 31;
    const float* st = style + b * SDIM;
    for (int ci = warp; ci < CIN; ci += 8) {
        const float* mw = mod_w + ci * SDIM;
        float sum = 0.f;
        for (int k = lane; k < SDIM; k += 32) sum += st[k] * mw[k];
        #pragma unroll
        for (int off = 16; off; off >>= 1)
            sum += __shfl_down_sync(0xffffffffu, sum, off);
        if (lane == 0) g_s[b * CIN + ci] = sum + mod_b[ci];
    }
}

// ---------------------------------------------------------------------------
// Stage 2: modulate + demodulate, transpose weights to [b][tap][ci][co].
// Also zero-inits this (b,co)'s border cells in g_o (written by k_border adds).
// ---------------------------------------------------------------------------
__global__ void k_wprep(const float* __restrict__ weight) {
    int co = blockIdx.x, b = blockIdx.y;
    __shared__ float vbuf[CIN * 9];
    __shared__ float red[256];
    const float scale = 1.0f / 48.0f;

    // zero border cells: plane0 row64 [0..64], plane1 row64 [0..63],
    // plane0 col64 rows[0..63], plane2 col64 rows[0..63]
    {
        float* base = g_o + (size_t)(b * COUT + co) * PSTR;
        int t = threadIdx.x;
        if (t < 65)       base[0 * PL + 64 * 68 + t] = 0.f;
        else if (t < 129) base[1 * PL + 64 * 68 + (t - 65)] = 0.f;
        else if (t < 193) base[0 * PL + (t - 129) * 68 + 64] = 0.f;
        else              base[2 * PL + (t - 193) * 68 + 64] = 0.f;  // t<257 handled below
        if (threadIdx.x == 255) base[2 * PL + 63 * 68 + 64] = 0.f;   // cover row 63 (t 193..255 = 63 rows)
    }

    float part = 0.f;
    for (int idx = threadIdx.x; idx < CIN * 9; idx += 256) {
        int ci = idx / 9;
        float v = scale * weight[co * CIN * 9 + idx] * g_s[b * CIN + ci];
        vbuf[idx] = v;
        part += v * v;
    }
    red[threadIdx.x] = part;
    __syncthreads();
    for (int s = 128; s; s >>= 1) {
        if (threadIdx.x < s) red[threadIdx.x] += red[threadIdx.x + s];
        __syncthreads();
    }
    float demod = rsqrtf(red[0] + 1e-8f);
    for (int idx = threadIdx.x; idx < CIN * 9; idx += 256) {
        int ci = idx / 9, t = idx - ci * 9;
        g_w[((b * 9 + t) * CIN + ci) * COUT + co] = vbuf[idx] * demod;
    }
}

// ---------------------------------------------------------------------------
// Stage 3: transposed conv, phase-specialized, 64x64 grid (border separate).
// ---------------------------------------------------------------------------
template <int TY, int TX>
__device__ __forceinline__ void tbody(
    const float* __restrict__ x,
    float (&xs)[2][CC][17][20], float (&ws)[2][CC][4][64],
    int b, int m0, int n0, int cob)
{
    constexpr int NT  = TY * TX;
    constexpr int XRa = 16 + TY - 1;
    constexpr int XCa = 16 + TX - 1;
    constexpr int PH  = ((TY == 2) ? 0 : 2) | ((TX == 2) ? 0 : 1);

    const int tid  = threadIdx.x;
    const int cog  = tid >> 5;
    const int lane = tid & 31;
    const int rrow = lane >> 1;
    const int cseg = lane & 1;
    const int y0   = m0 - (TY - 1);
    const int xc0  = n0 - (TX - 1);

    u64 acc[4][8];
    #pragma unroll
    for (int j = 0; j < 4; j++)
        #pragma unroll
        for (int i = 0; i < 8; i++) acc[j][i] = 0ull;

    auto issue = [&](int ci0, int buf) {
        const float* xb = x + ((size_t)b * CIN + ci0) * 4096;
        for (int idx = tid; idx < CC * XRa * XCa; idx += 256) {
            int cc  = idx / (XRa * XCa);
            int rem = idx - cc * (XRa * XCa);
            int r   = rem / XCa, c = rem - r * XCa;
            int y   = y0 + r, xx = xc0 + c;
            bool ok = ((unsigned)y < 64u) & ((unsigned)xx < 64u);
            cpa4(&xs[buf][cc][r][c], xb + cc * 4096 + (y & 63) * 64 + (xx & 63), ok);
        }
        for (int idx = tid; idx < CC * NT * 16; idx += 256) {
            int c4 = idx & 15;
            int t  = (idx >> 4) % NT;
            int cc = (idx >> 4) / NT;
            int ry = t / TX, rx = t - ry * TX;
            int ky = (TY == 2) ? (2 - 2 * ry) : 1;
            int kx = (TX == 2) ? (2 - 2 * rx) : 1;
            cpa16(&ws[buf][cc][t][c4 * 4],
                  g_w + (((size_t)b * 9 + ky * 3 + kx) * CIN + ci0 + cc) * COUT + cob + c4 * 4);
        }
    };

    issue(0, 0);
    cp_commit();
    int cur = 0;
    for (int c0 = 0; c0 < CIN / CC; c0++) {
        cp_wait0();
        __syncthreads();
        if (c0 + 1 < CIN / CC) { issue((c0 + 1) * CC, cur ^ 1); cp_commit(); }

        #pragma unroll 1
        for (int cc = 0; cc < CC; cc++) {
            #pragma unroll
            for (int ry = 0; ry < TY; ry++) {
                const float4* xp =
                    reinterpret_cast<const float4*>(&xs[cur][cc][rrow + ry][cseg * 8]);
                float4 q0 = xp[0], q1 = xp[1];
                u64 xx2[9];
                xx2[0] = dup2(q0.x); xx2[1] = dup2(q0.y);
                xx2[2] = dup2(q0.z); xx2[3] = dup2(q0.w);
                xx2[4] = dup2(q1.x); xx2[5] = dup2(q1.y);
                xx2[6] = dup2(q1.z); xx2[7] = dup2(q1.w);
                if (TX == 2) { float4 q2 = xp[2]; xx2[8] = dup2(q2.x); }
                #pragma unroll
                for (int rx = 0; rx < TX; rx++) {
                    const u64* wp =
                        reinterpret_cast<const u64*>(&ws[cur][cc][ry * TX + rx][cog * 8]);
                    u64 w0 = wp[0], w1 = wp[1], w2 = wp[2], w3 = wp[3];
                    #pragma unroll
                    for (int i = 0; i < 8; i++) {
                        fma2(acc[0][i], w0, xx2[i + rx]);
                        fma2(acc[1][i], w1, xx2[i + rx]);
                        fma2(acc[2][i], w2, xx2[i + rx]);
                        fma2(acc[3][i], w3, xx2[i + rx]);
                    }
                }
            }
        }
        cur ^= 1;
    }

    int m = m0 + rrow;
    size_t base = (size_t)(b * COUT + cob + cog * 8) * PSTR
                + (size_t)PH * PL + m * 68 + n0 + cseg * 8;
    #pragma unroll
    for (int j2 = 0; j2 < 4; j2++) {
        float lo[8], hi[8];
        #pragma unroll
        for (int i = 0; i < 8; i++) {
            float2 f = unpk(acc[j2][i]);
            lo[i] = f.x; hi[i] = f.y;
        }
        float* p0 = g_o + base + (size_t)(2 * j2) * PSTR;
        float* p1 = p0 + PSTR;
        *(float4*)(p0)     = make_float4(lo[0], lo[1], lo[2], lo[3]);
        *(float4*)(p0 + 4) = make_float4(lo[4], lo[5], lo[6], lo[7]);
        *(float4*)(p1)     = make_float4(hi[0], hi[1], hi[2], hi[3]);
        *(float4*)(p1 + 4) = make_float4(hi[4], hi[5], hi[6], hi[7]);
    }
}

__global__ __launch_bounds__(256, 2)
void k_tconv_all(const float* __restrict__ x) {
    __shared__ float xs[2][CC][17][20];
    __shared__ float ws[2][CC][4][64];
    int ph  = blockIdx.y >> 1;
    int cob = (blockIdx.y & 1) * 64;
    int b   = blockIdx.z;
    int m0  = (blockIdx.x >> 2) * 16;
    int n0  = (blockIdx.x & 3) * 16;
    switch (ph) {
        case 0:  tbody<2, 2>(x, xs, ws, b, m0, n0, cob); break;
        case 1:  tbody<2, 1>(x, xs, ws, b, m0, n0, cob); break;
        case 2:  tbody<1, 2>(x, xs, ws, b, m0, n0, cob); break;
        default: tbody<1, 1>(x, xs, ws, b, m0, n0, cob); break;
    }
}

// ---------------------------------------------------------------------------
// Stage 3b (v3): border strips, ci-split x8, cp.async pipelined, atomicAdd.
//   row p=128: q=2n  -> xr[n-1]*W(2,2) + xr[n]*W(2,0);  q=2n+1 -> xr[n]*W(2,1)
//   col q=128: p=2m  -> xc[m-1]*W(2,2) + xc[m]*W(0,2);  p=2m+1 -> xc[m]*W(1,2)
// Block: (b, side, cout-half, ci-split). Threads: 256 = 64 co x 4 q-segments.
// ---------------------------------------------------------------------------
__global__ __launch_bounds__(256)
void k_border(const float* __restrict__ x) {
    int blk   = blockIdx.x;
    int split = blk & (NSPL - 1);
    int cog   = (blk >> 3) & 1;
    int side  = (blk >> 4) & 1;
    int b     = blk >> 5;

    __shared__ float xsb[2][CC][66];
    __shared__ float wsb[2][3][CC][64];

    const int tid  = threadIdx.x;
    const int co_l = tid & 63;
    const int qs   = tid >> 6;
    const int q0   = qs * 33;
    const int co   = cog * 64 + co_l;

    const int tA = 8;
    const int tB = side ? 2 : 6;
    const int tC = side ? 5 : 7;
    const float* W  = g_w + (size_t)b * 9 * CIN * COUT;
    const float* xb = x + (size_t)b * CIN * 4096;
    const int ci_base = split * (CIN / NSPL);   // 32 ci per split

    // zero pads (constant across chunks, both buffers)
    if (tid < 4 * CC) {
        int buf = tid & 1, cc = (tid >> 2);
        xsb[buf][cc & 7][((tid >> 1) & 1) ? 65 : 0] = 0.f;
    }
    __syncthreads();

    auto issue = [&](int ci0, int buf) {
        for (int idx = tid; idx < CC * 64; idx += 256) {
            int cc = idx >> 6, n = idx & 63;
            const float* xp = xb + (size_t)(ci0 + cc) * 4096;
            cpa4(&xsb[buf][cc][1 + n], side ? (xp + n * 64 + 63) : (xp + 63 * 64 + n), true);
        }
        for (int idx = tid; idx < 3 * CC * 16; idx += 256) {
            int c4 = idx & 15;
            int cc = (idx >> 4) & 7;
            int t3 = idx >> 7;
            int tap = (t3 == 0) ? tA : (t3 == 1) ? tB : tC;
            cpa16(&wsb[buf][t3][cc][c4 * 4],
                  W + ((size_t)tap * CIN + ci0 + cc) * COUT + cog * 64 + c4 * 4);
        }
    };

    float acc[33];
    #pragma unroll
    for (int k = 0; k < 33; k++) acc[k] = 0.f;

    issue(ci_base, 0);
    cp_commit();
    int cur = 0;
    constexpr int NCH = (CIN / NSPL) / CC;   // 4
    for (int c0 = 0; c0 < NCH; c0++) {
        cp_wait0();
        __syncthreads();
        if (c0 + 1 < NCH) { issue(ci_base + (c0 + 1) * CC, cur ^ 1); cp_commit(); }

        #pragma unroll
        for (int cc = 0; cc < CC; cc++) {
            float wA = wsb[cur][0][cc][co_l];
            float wB = wsb[cur][1][cc][co_l];
            float wC = wsb[cur][2][cc][co_l];
            #pragma unroll
            for (int k = 0; k < 33; k++) {
                int q = q0 + k;
                int n = q >> 1;
                if (q <= 128) {
                    if ((q & 1) == 0)
                        acc[k] = fmaf(wA, xsb[cur][cc][n], fmaf(wB, xsb[cur][cc][n + 1], acc[k]));
                    else
                        acc[k] = fmaf(wC, xsb[cur][cc][n + 1], acc[k]);
                }
            }
        }
        __syncthreads();
        cur ^= 1;
    }

    size_t cb = (size_t)(b * COUT + co) * PSTR;
    #pragma unroll
    for (int k = 0; k < 33; k++) {
        int q = q0 + k;
        if (q > 128) continue;
        if (side == 0) {
            int plane = q & 1;
            atomicAdd(&g_o[cb + (size_t)plane * PL + 64 * 68 + (q >> 1)], acc[k]);
        } else {
            if (q == 128) continue;
            int plane = (q & 1) * 2;
            atomicAdd(&g_o[cb + (size_t)plane * PL + (q >> 1) * 68 + 64], acc[k]);
        }
    }
}

// ---------------------------------------------------------------------------
// Stage 4: separable 4x4 blur, gathering from phase planes.
// ---------------------------------------------------------------------------
__global__ __launch_bounds__(256)
void k_blur(float* __restrict__ out) {
    int bc = blockIdx.x;
    int u0 = blockIdx.y * 16;
    __shared__ float os[19][132];
    __shared__ float hs[19][132];
    const float bk[4] = {0.25f, 0.75f, 0.75f, 0.25f};
    const float* src = g_o + (size_t)bc * PSTR;

    for (int idx = threadIdx.x; idx < 19 * 132; idx += 256) {
        int r = idx / 132, c = idx - r * 132;
        int gr = u0 - 1 + r, gc = c - 1;
        float v = 0.f;
        if ((unsigned)gr < 129u && (unsigned)gc < 129u) {
            int plane = ((gr & 1) << 1) | (gc & 1);
            v = src[(size_t)plane * PL + (gr >> 1) * 68 + (gc >> 1)];
        }
        os[r][c] = v;
    }
    __syncthreads();
    for (int idx = threadIdx.x; idx < 19 * 128; idx += 256) {
        int r = idx >> 7, v = idx & 127;
        float h = 0.f;
        #pragma unroll
        for (int s = 0; s < 4; s++) h += bk[s] * os[r][v + 3 - s];
        hs[r][v] = h;
    }
    __syncthreads();
    for (int idx = threadIdx.x; idx < 16 * 128; idx += 256) {
        int ul = idx >> 7, v = idx & 127;
        float o = 0.f;
        #pragma unroll
        for (int t = 0; t < 4; t++) o += bk[t] * hs[ul + 3 - t][v];
        out[((size_t)bc * HOUT + u0 + ul) * HOUT + v] = o;
    }
}

// ---------------------------------------------------------------------------
extern "C" void kernel_launch(void* const* d_in, const int* in_sizes, int n_in,
                              void* d_out, int out_size) {
    const float* x      = (const float*)d_in[0];
    const float* style  = (const float*)d_in[1];
    const float* weight = (const float*)d_in[2];
    const float* mod_w  = (const float*)d_in[3];
    const float* mod_b  = (const float*)d_in[4];
    float* out = (float*)d_out;

    k_style<<<B, 256>>>(style, mod_w, mod_b);
    k_wprep<<<dim3(COUT, B), 256>>>(weight);
    k_tconv_all<<<dim3(16, 8, B), 256>>>(x);
    k_border<<<dim3(B * 4 * NSPL), 256>>>(x);
    k_blur<<<dim3(B * COUT, 8), 256>>>(out);
}

// round 8
// speedup vs baseline: 2.0478x; 1.0529x over previous
#include <cuda_runtime.h>
#include <cuda_bf16.h>

#define B    16
#define CIN  256
#define COUT 128
#define SDIM 512
#define HOUT 128
#define PL   4420          // 65*68 padded phase plane
#define PSTR (4*PL)

typedef unsigned long long u64;
typedef unsigned int u32;

// Scratch
__device__ float g_s[B * CIN];
__device__ __align__(128) float g_o[(size_t)B * COUT * 4 * PL];
__device__ __align__(128) float g_t[(size_t)B * 64 * 9 * 64 * COUT];   // [b][y][tap][x][co]
__device__ __align__(128) __nv_bfloat16 g_wh[(size_t)B * 9 * COUT * CIN];
__device__ __align__(128) __nv_bfloat16 g_wl[(size_t)B * 9 * COUT * CIN];
__device__ __align__(128) __nv_bfloat16 g_xh[(size_t)B * 4096 * CIN];  // [b][s][ci]
__device__ __align__(128) __nv_bfloat16 g_xl[(size_t)B * 4096 * CIN];

__device__ __forceinline__ u32 su32(const void* p) {
    return (u32)__cvta_generic_to_shared(p);
}
__device__ __forceinline__ void cpa16s(u32 dst, const void* src) {
    asm volatile("cp.async.ca.shared.global [%0],[%1],16;\n" :: "r"(dst), "l"(src));
}
__device__ __forceinline__ void cp_commit() { asm volatile("cp.async.commit_group;"); }

__device__ __forceinline__ void ldm_x4(u32* r, u32 addr) {
    asm volatile("ldmatrix.sync.aligned.m8n8.x4.shared.b16 {%0,%1,%2,%3}, [%4];"
                 : "=r"(r[0]), "=r"(r[1]), "=r"(r[2]), "=r"(r[3]) : "r"(addr));
}
__device__ __forceinline__ void mma_bf16(float* d, const u32* a, u32 b0, u32 b1) {
    asm volatile("mma.sync.aligned.m16n8k16.row.col.f32.bf16.bf16.f32 "
                 "{%0,%1,%2,%3},{%4,%5,%6,%7},{%8,%9},{%0,%1,%2,%3};"
                 : "+f"(d[0]), "+f"(d[1]), "+f"(d[2]), "+f"(d[3])
                 : "r"(a[0]), "r"(a[1]), "r"(a[2]), "r"(a[3]), "r"(b0), "r"(b1));
}

// ---------------------------------------------------------------------------
// Stage 1: s[b,ci] = style . mod_w^T + mod_b
// ---------------------------------------------------------------------------
__global__ void k_style(const float* __restrict__ style,
                        const float* __restrict__ mod_w,
                        const float* __restrict__ mod_b) {
    int b = blockIdx.x;
    int warp = threadIdx.x >> 5, lane = threadIdx.x & 31;
    const float* st = style + b * SDIM;
    for (int ci = warp; ci < CIN; ci += 8) {
        const float* mw = mod_w + ci * SDIM;
        float sum = 0.f;
        for (int k = lane; k < SDIM; k += 32) sum += st[k] * mw[k];
        #pragma unroll
        for (int off = 16; off; off >>= 1)
            sum += __shfl_down_sync(0xffffffffu, sum, off);
        if (lane == 0) g_s[b * CIN + ci] = sum + mod_b[ci];
    }
}

// ---------------------------------------------------------------------------
// Stage 2: modulate + demodulate -> bf16 hi/lo weights [b][tap][co][ci]
// ---------------------------------------------------------------------------
__global__ void k_wprep(const float* __restrict__ weight) {
    int co = blockIdx.x, b = blockIdx.y;
    __shared__ float vbuf[CIN * 9];
    __shared__ float red[256];
    const float scale = 1.0f / 48.0f;

    float part = 0.f;
    for (int idx = threadIdx.x; idx < CIN * 9; idx += 256) {
        int ci = idx / 9;
        float v = scale * weight[co * CIN * 9 + idx] * g_s[b * CIN + ci];
        vbuf[idx] = v;
        part += v * v;
    }
    red[threadIdx.x] = part;
    __syncthreads();
    for (int s = 128; s; s >>= 1) {
        if (threadIdx.x < s) red[threadIdx.x] += red[threadIdx.x + s];
        __syncthreads();
    }
    float demod = rsqrtf(red[0] + 1e-8f);
    for (int idx = threadIdx.x; idx < CIN * 9; idx += 256) {
        int ci = idx / 9, t = idx - ci * 9;
        float v = vbuf[idx] * demod;
        __nv_bfloat16 hi = __float2bfloat16(v);
        __nv_bfloat16 lo = __float2bfloat16(v - __bfloat162float(hi));
        size_t o = (((size_t)b * 9 + t) * COUT + co) * CIN + ci;
        g_wh[o] = hi;
        g_wl[o] = lo;
    }
}

// ---------------------------------------------------------------------------
// Stage 2b: transpose x -> [b][spatial][ci] bf16 hi/lo
// ---------------------------------------------------------------------------
__global__ __launch_bounds__(256)
void k_xprep(const float* __restrict__ x) {
    __shared__ float tile[32][129];
    int sc0 = blockIdx.x * 128;
    int b   = blockIdx.y;
    int tid = threadIdx.x;
    for (int ci0 = 0; ci0 < CIN; ci0 += 32) {
        __syncthreads();
        for (int i = tid; i < 32 * 128; i += 256) {
            int cir = i >> 7, sc = i & 127;
            tile[cir][sc] = x[((size_t)(b * CIN + ci0 + cir)) * 4096 + sc0 + sc];
        }
        __syncthreads();
        int ciL = tid & 31;
        int scg = tid >> 5;
        for (int j = 0; j < 16; j++) {
            int sc = scg * 16 + j;
            float v = tile[ciL][sc];
            __nv_bfloat16 hi = __float2bfloat16(v);
            __nv_bfloat16 lo = __float2bfloat16(v - __bfloat162float(hi));
            size_t o = ((size_t)b * 4096 + sc0 + sc) * CIN + ci0 + ciL;
            g_xh[o] = hi;
            g_xl[o] = lo;
        }
    }
}

// ---------------------------------------------------------------------------
// Stage 3: warp-MMA GEMM. Block = (mtile 128 spatial, tap, b).
// T_t[s, co] += X[s, ci] * W_t[ci, co], 3-pass bf16 split:
//   pass 0: xh*wh, pass 1: xl*wh, pass 2: xh*wl
// Warp tile 64m x 32n; mma.m16n8k16 row.col, f32 accum.
// ---------------------------------------------------------------------------
__global__ __launch_bounds__(256)
void k_gemm() {
    __shared__ __nv_bfloat16 As[2][128][40];   // [s][ci], 80B row stride
    __shared__ __nv_bfloat16 Bs[2][128][40];   // [co][ci]

    int mt = blockIdx.x, t = blockIdx.y, b = blockIdx.z;
    int s0 = mt * 128;
    int tid = threadIdx.x, wid = tid >> 5, lane = tid & 31;
    int wm = wid & 1, wn = wid >> 1;

    const __nv_bfloat16* xh = g_xh + ((size_t)b * 4096 + s0) * CIN;
    const __nv_bfloat16* xl = g_xl + ((size_t)b * 4096 + s0) * CIN;
    const __nv_bfloat16* wh = g_wh + ((size_t)b * 9 + t) * COUT * CIN;
    const __nv_bfloat16* wl = g_wl + ((size_t)b * 9 + t) * COUT * CIN;

    float acc[4][4][4];
    #pragma unroll
    for (int i = 0; i < 4; i++)
        #pragma unroll
        for (int j = 0; j < 4; j++)
            #pragma unroll
            for (int k = 0; k < 4; k++) acc[i][j][k] = 0.f;

    auto issue = [&](int c, int buf) {
        int p = c >> 3, k0 = (c & 7) * 32;
        const __nv_bfloat16* A  = (p == 1) ? xl : xh;
        const __nv_bfloat16* Bw = (p == 2) ? wl : wh;
        #pragma unroll
        for (int i = 0; i < 2; i++) {
            int id = tid * 2 + i;
            int row = id >> 2, seg = id & 3;
            cpa16s(su32(&As[buf][row][seg * 8]), A  + (size_t)row * CIN + k0 + seg * 8);
            cpa16s(su32(&Bs[buf][row][seg * 8]), Bw + (size_t)row * CIN + k0 + seg * 8);
        }
        cp_commit();
    };

    issue(0, 0);
    int cur = 0;
    #pragma unroll 1
    for (int c = 0; c < 24; c++) {
        if (c < 23) {
            issue(c + 1, cur ^ 1);
            asm volatile("cp.async.wait_group 1;");
        } else {
            asm volatile("cp.async.wait_group 0;");
        }
        __syncthreads();

        #pragma unroll
        for (int ks = 0; ks < 2; ks++) {
            u32 bf[2][4];
            #pragma unroll
            for (int ng = 0; ng < 2; ng++) {
                int nb = wn * 32 + ng * 16;
                int row = nb + (lane & 7) + ((lane & 16) ? 8 : 0);
                int col = ks * 16 + ((lane & 8) ? 8 : 0);
                ldm_x4(bf[ng], su32(&Bs[cur][row][col]));
            }
            #pragma unroll
            for (int mf = 0; mf < 4; mf++) {
                int mb = wm * 64 + mf * 16;
                int row = mb + (lane & 15);
                int col = ks * 16 + ((lane & 16) ? 8 : 0);
                u32 af[4];
                ldm_x4(af, su32(&As[cur][row][col]));
                #pragma unroll
                for (int ng = 0; ng < 2; ng++) {
                    mma_bf16(acc[mf][ng * 2 + 0], af, bf[ng][0], bf[ng][1]);
                    mma_bf16(acc[mf][ng * 2 + 1], af, bf[ng][2], bf[ng][3]);
                }
            }
        }
        __syncthreads();
        cur ^= 1;
    }

    // epilogue: write T_t tile [b][y][tap][x][co]
    #pragma unroll
    for (int mf = 0; mf < 4; mf++) {
        int r0 = s0 + wm * 64 + mf * 16 + (lane >> 2);
        #pragma unroll
        for (int nf = 0; nf < 4; nf++) {
            int co = wn * 32 + nf * 8 + (lane & 3) * 2;
            #pragma unroll
            for (int h = 0; h < 2; h++) {
                int s = r0 + h * 8;
                int y = s >> 6, xx = s & 63;
                float* dst = g_t + ((((size_t)(b * 64 + y)) * 9 + t) * 64 + xx) * COUT + co;
                *(float2*)dst = make_float2(acc[mf][nf][h * 2], acc[mf][nf][h * 2 + 1]);
            }
        }
    }
}

// ---------------------------------------------------------------------------
// Stage 4: tap combine -> phase planes (covers borders; no atomics).
//   plane0 (p=2m,q=2n):   t0@(m,n) t2@(m,n-1) t6@(m-1,n) t8@(m-1,n-1)
//   plane1 (p=2m,q=2n+1): t1@(m,n) t7@(m-1,n)
//   plane2 (p=2m+1,q=2n): t3@(m,n) t5@(m,n-1)
//   plane3:               t4@(m,n)
// ---------------------------------------------------------------------------
__global__ __launch_bounds__(256)
void k_comb() {
    int m = blockIdx.x;            // 0..64
    int b = blockIdx.y;
    int tid = threadIdx.x;
    int co = tid & 127;
    int nh = tid >> 7;
    const float* Ty  = g_t + ((size_t)(b * 64 + m) * 9) * 64 * COUT;
    const float* Tym = g_t + ((size_t)(b * 64 + m - 1) * 9) * 64 * COUT;
    bool hy = (m <= 63), hym = (m >= 1);
    float* ob = g_o + (size_t)(b * COUT + co) * PSTR;

    for (int n = nh; n <= 64; n += 2) {
        bool hx = (n <= 63), hxm = (n >= 1);
        float p0 = 0.f, p1 = 0.f, p2 = 0.f, p3 = 0.f;
        if (hy) {
            if (hx) {
                p0 += __ldg(Ty + ((size_t)(0 * 64 + n)) * COUT + co);
                p1 += __ldg(Ty + ((size_t)(1 * 64 + n)) * COUT + co);
                p2 += __ldg(Ty + ((size_t)(3 * 64 + n)) * COUT + co);
                p3 += __ldg(Ty + ((size_t)(4 * 64 + n)) * COUT + co);
            }
            if (hxm) {
                p0 += __ldg(Ty + ((size_t)(2 * 64 + n - 1)) * COUT + co);
                p2 += __ldg(Ty + ((size_t)(5 * 64 + n - 1)) * COUT + co);
            }
        }
        if (hym) {
            if (hx) {
                p0 += __ldg(Tym + ((size_t)(6 * 64 + n)) * COUT + co);
                p1 += __ldg(Tym + ((size_t)(7 * 64 + n)) * COUT + co);
            }
            if (hxm) p0 += __ldg(Tym + ((size_t)(8 * 64 + n - 1)) * COUT + co);
        }
        ob[0 * PL + m * 68 + n] = p0;
        if (n <= 63) ob[1 * PL + m * 68 + n] = p1;
        if (m <= 63) ob[2 * PL + m * 68 + n] = p2;
        if (m <= 63 && n <= 63) ob[3 * PL + m * 68 + n] = p3;
    }
}

// ---------------------------------------------------------------------------
// Stage 5: separable 4x4 blur from phase planes.
// ---------------------------------------------------------------------------
__global__ __launch_bounds__(256)
void k_blur(float* __restrict__ out) {
    int bc = blockIdx.x;
    int u0 = blockIdx.y * 16;
    __shared__ float os[19][132];
    __shared__ float hs[19][132];
    const float bk[4] = {0.25f, 0.75f, 0.75f, 0.25f};
    const float* src = g_o + (size_t)bc * PSTR;

    for (int idx = threadIdx.x; idx < 19 * 132; idx += 256) {
        int r = idx / 132, c = idx - r * 132;
        int gr = u0 - 1 + r, gc = c - 1;
        float v = 0.f;
        if ((unsigned)gr < 129u && (unsigned)gc < 129u) {
            int plane = ((gr & 1) << 1) | (gc & 1);
            v = src[(size_t)plane * PL + (gr >> 1) * 68 + (gc >> 1)];
        }
        os[r][c] = v;
    }
    __syncthreads();
    for (int idx = threadIdx.x; idx < 19 * 128; idx += 256) {
        int r = idx >> 7, v = idx & 127;
        float h = 0.f;
        #pragma unroll
        for (int s = 0; s < 4; s++) h += bk[s] * os[r][v + 3 - s];
        hs[r][v] = h;
    }
    __syncthreads();
    for (int idx = threadIdx.x; idx < 16 * 128; idx += 256) {
        int ul = idx >> 7, v = idx & 127;
        float o = 0.f;
        #pragma unroll
        for (int t = 0; t < 4; t++) o += bk[t] * hs[ul + 3 - t][v];
        out[((size_t)bc * HOUT + u0 + ul) * HOUT + v] = o;
    }
}

// ---------------------------------------------------------------------------
extern "C" void kernel_launch(void* const* d_in, const int* in_sizes, int n_in,
                              void* d_out, int out_size) {
    const float* x      = (const float*)d_in[0];
    const float* style  = (const float*)d_in[1];
    const float* weight = (const float*)d_in[2];
    const float* mod_w  = (const float*)d_in[3];
    const float* mod_b  = (const float*)d_in[4];
    float* out = (float*)d_out;

    k_style<<<B, 256>>>(style, mod_w, mod_b);
    k_xprep<<<dim3(32, B), 256>>>(x);
    k_wprep<<<dim3(COUT, B), 256>>>(weight);
    k_gemm<<<dim3(32, 9, B), 256>>>();
    k_comb<<<dim3(65, B), 256>>>();
    k_blur<<<dim3(B * COUT, 8), 256>>>(out);
}

// round 9
// speedup vs baseline: 2.1992x; 1.0739x over previous
#include <cuda_runtime.h>
#include <cuda_bf16.h>

#define B    16
#define CIN  256
#define COUT 128
#define SDIM 512
#define HOUT 128
#define PL   4420          // 65*68 padded phase plane
#define PSTR (4*PL)

typedef unsigned long long u64;
typedef unsigned int u32;

// Scratch
__device__ float g_s[B * CIN];
__device__ __align__(128) float g_o[(size_t)B * COUT * 4 * PL];
__device__ __align__(128) float g_t[(size_t)B * 64 * 9 * 64 * COUT];   // [b][y][tap][x][co]
__device__ __align__(128) __nv_bfloat16 g_wh[(size_t)B * 9 * COUT * CIN];
__device__ __align__(128) __nv_bfloat16 g_wl[(size_t)B * 9 * COUT * CIN];
__device__ __align__(128) __nv_bfloat16 g_xh[(size_t)B * 4096 * CIN];  // [b][s][ci]
__device__ __align__(128) __nv_bfloat16 g_xl[(size_t)B * 4096 * CIN];

__device__ __forceinline__ u32 su32(const void* p) {
    return (u32)__cvta_generic_to_shared(p);
}
__device__ __forceinline__ void cpa16s(u32 dst, const void* src) {
    asm volatile("cp.async.ca.shared.global [%0],[%1],16;\n" :: "r"(dst), "l"(src));
}
__device__ __forceinline__ void cp_commit() { asm volatile("cp.async.commit_group;"); }

__device__ __forceinline__ void ldm_x4(u32* r, u32 addr) {
    asm volatile("ldmatrix.sync.aligned.m8n8.x4.shared.b16 {%0,%1,%2,%3}, [%4];"
                 : "=r"(r[0]), "=r"(r[1]), "=r"(r[2]), "=r"(r[3]) : "r"(addr));
}
__device__ __forceinline__ void mma_bf16(float* d, const u32* a, u32 b0, u32 b1) {
    asm volatile("mma.sync.aligned.m16n8k16.row.col.f32.bf16.bf16.f32 "
                 "{%0,%1,%2,%3},{%4,%5,%6,%7},{%8,%9},{%0,%1,%2,%3};"
                 : "+f"(d[0]), "+f"(d[1]), "+f"(d[2]), "+f"(d[3])
                 : "r"(a[0]), "r"(a[1]), "r"(a[2]), "r"(a[3]), "r"(b0), "r"(b1));
}

// ---------------------------------------------------------------------------
// Stage 1: s[b,ci] = style . mod_w^T + mod_b
// ---------------------------------------------------------------------------
__global__ void k_style(const float* __restrict__ style,
                        const float* __restrict__ mod_w,
                        const float* __restrict__ mod_b) {
    int b = blockIdx.x;
    int warp = threadIdx.x >> 5, lane = threadIdx.x & 31;
    const float* st = style + b * SDIM;
    for (int ci = warp; ci < CIN; ci += 8) {
        const float* mw = mod_w + ci * SDIM;
        float sum = 0.f;
        for (int k = lane; k < SDIM; k += 32) sum += st[k] * mw[k];
        #pragma unroll
        for (int off = 16; off; off >>= 1)
            sum += __shfl_down_sync(0xffffffffu, sum, off);
        if (lane == 0) g_s[b * CIN + ci] = sum + mod_b[ci];
    }
}

// ---------------------------------------------------------------------------
// Stage 2: modulate + demodulate -> bf16 hi/lo weights [b][tap][co][ci]
// ---------------------------------------------------------------------------
__global__ void k_wprep(const float* __restrict__ weight) {
    int co = blockIdx.x, b = blockIdx.y;
    __shared__ float vbuf[CIN * 9];
    __shared__ float red[256];
    const float scale = 1.0f / 48.0f;

    float part = 0.f;
    for (int idx = threadIdx.x; idx < CIN * 9; idx += 256) {
        int ci = idx / 9;
        float v = scale * weight[co * CIN * 9 + idx] * g_s[b * CIN + ci];
        vbuf[idx] = v;
        part += v * v;
    }
    red[threadIdx.x] = part;
    __syncthreads();
    for (int s = 128; s; s >>= 1) {
        if (threadIdx.x < s) red[threadIdx.x] += red[threadIdx.x + s];
        __syncthreads();
    }
    float demod = rsqrtf(red[0] + 1e-8f);
    for (int idx = threadIdx.x; idx < CIN * 9; idx += 256) {
        int ci = idx / 9, t = idx - ci * 9;
        float v = vbuf[idx] * demod;
        __nv_bfloat16 hi = __float2bfloat16(v);
        __nv_bfloat16 lo = __float2bfloat16(v - __bfloat162float(hi));
        size_t o = (((size_t)b * 9 + t) * COUT + co) * CIN + ci;
        g_wh[o] = hi;
        g_wl[o] = lo;
    }
}

// ---------------------------------------------------------------------------
// Stage 2b: transpose x -> [b][spatial][ci] bf16 hi/lo, packed u32 stores
// ---------------------------------------------------------------------------
__global__ __launch_bounds__(256)
void k_xprep(const float* __restrict__ x) {
    __shared__ float tile[32][129];
    int sc0 = blockIdx.x * 128;
    int b   = blockIdx.y;
    int tid = threadIdx.x;
    for (int ci0 = 0; ci0 < CIN; ci0 += 32) {
        __syncthreads();
        for (int i = tid; i < 32 * 128; i += 256) {
            int cir = i >> 7, sc = i & 127;
            tile[cir][sc] = x[((size_t)(b * CIN + ci0 + cir)) * 4096 + sc0 + sc];
        }
        __syncthreads();
        for (int it = tid; it < 128 * 16; it += 256) {
            int sc = it >> 4, cu = it & 15;
            float v0 = tile[cu * 2][sc], v1 = tile[cu * 2 + 1][sc];
            __nv_bfloat16 h0 = __float2bfloat16(v0);
            __nv_bfloat16 h1 = __float2bfloat16(v1);
            __nv_bfloat16 l0 = __float2bfloat16(v0 - __bfloat162float(h0));
            __nv_bfloat16 l1 = __float2bfloat16(v1 - __bfloat162float(h1));
            size_t rowo = ((size_t)b * 4096 + sc0 + sc) * CIN + ci0;
            __nv_bfloat162 hp; hp.x = h0; hp.y = h1;
            __nv_bfloat162 lp; lp.x = l0; lp.y = l1;
            ((__nv_bfloat162*)(g_xh + rowo))[cu] = hp;
            ((__nv_bfloat162*)(g_xl + rowo))[cu] = lp;
        }
    }
}

// ---------------------------------------------------------------------------
// Stage 3: warp-MMA GEMM, single K loop, 3 products per chunk.
// Block = (mtile 128 spatial, tap, b). T_t[s,co] = X[s,:]*W_t[:,co]
//   products: ah*wh + al*wh + ah*wl  (bf16 hi/lo split)
// smem: Ah/Al/Bh/Bl [2][128][40] bf16 (80KB dynamic).
// ---------------------------------------------------------------------------
#define TILE 5120   // elems per buffer (128*40)
__global__ __launch_bounds__(256)
void k_gemm() {
    extern __shared__ __nv_bfloat16 sm[];
    __nv_bfloat16* Ah = sm;
    __nv_bfloat16* Al = sm + 2 * TILE;
    __nv_bfloat16* Bh = sm + 4 * TILE;
    __nv_bfloat16* Bl = sm + 6 * TILE;

    int mt = blockIdx.x, t = blockIdx.y, b = blockIdx.z;
    int s0 = mt * 128;
    int tid = threadIdx.x, wid = tid >> 5, lane = tid & 31;
    int wm = wid & 1, wn = wid >> 1;

    const __nv_bfloat16* xh = g_xh + ((size_t)b * 4096 + s0) * CIN;
    const __nv_bfloat16* xl = g_xl + ((size_t)b * 4096 + s0) * CIN;
    const __nv_bfloat16* wh = g_wh + ((size_t)b * 9 + t) * COUT * CIN;
    const __nv_bfloat16* wl = g_wl + ((size_t)b * 9 + t) * COUT * CIN;

    float acc[4][4][4];
    #pragma unroll
    for (int i = 0; i < 4; i++)
        #pragma unroll
        for (int j = 0; j < 4; j++)
            #pragma unroll
            for (int k = 0; k < 4; k++) acc[i][j][k] = 0.f;

    auto issue = [&](int c, int buf) {
        int k0 = c * 32;
        #pragma unroll
        for (int i = 0; i < 2; i++) {
            int id = tid * 2 + i;
            int row = id >> 2, seg = id & 3;
            size_t go = (size_t)row * CIN + k0 + seg * 8;
            u32 so = buf * TILE + row * 40 + seg * 8;
            cpa16s(su32(Ah + so), xh + go);
            cpa16s(su32(Al + so), xl + go);
            cpa16s(su32(Bh + so), wh + go);
            cpa16s(su32(Bl + so), wl + go);
        }
        cp_commit();
    };

    issue(0, 0);
    int cur = 0;
    #pragma unroll 1
    for (int c = 0; c < 8; c++) {
        if (c < 7) {
            issue(c + 1, cur ^ 1);
            asm volatile("cp.async.wait_group 1;");
        } else {
            asm volatile("cp.async.wait_group 0;");
        }
        __syncthreads();

        #pragma unroll
        for (int ks = 0; ks < 2; ks++) {
            u32 bh[2][4], bl[2][4];
            #pragma unroll
            for (int ng = 0; ng < 2; ng++) {
                int row = wn * 32 + ng * 16 + (lane & 7) + ((lane & 16) ? 8 : 0);
                int col = ks * 16 + ((lane & 8) ? 8 : 0);
                u32 so = cur * TILE + row * 40 + col;
                ldm_x4(bh[ng], su32(Bh + so));
                ldm_x4(bl[ng], su32(Bl + so));
            }
            #pragma unroll
            for (int mf = 0; mf < 4; mf++) {
                int row = wm * 64 + mf * 16 + (lane & 15);
                int col = ks * 16 + ((lane & 16) ? 8 : 0);
                u32 so = cur * TILE + row * 40 + col;
                u32 ah[4], al[4];
                ldm_x4(ah, su32(Ah + so));
                ldm_x4(al, su32(Al + so));
                #pragma unroll
                for (int ng = 0; ng < 2; ng++) {
                    mma_bf16(acc[mf][ng * 2 + 0], ah, bh[ng][0], bh[ng][1]);
                    mma_bf16(acc[mf][ng * 2 + 1], ah, bh[ng][2], bh[ng][3]);
                    mma_bf16(acc[mf][ng * 2 + 0], al, bh[ng][0], bh[ng][1]);
                    mma_bf16(acc[mf][ng * 2 + 1], al, bh[ng][2], bh[ng][3]);
                    mma_bf16(acc[mf][ng * 2 + 0], ah, bl[ng][0], bl[ng][1]);
                    mma_bf16(acc[mf][ng * 2 + 1], ah, bl[ng][2], bl[ng][3]);
                }
            }
        }
        __syncthreads();
        cur ^= 1;
    }

    // epilogue: write T_t tile [b][y][tap][x][co]
    #pragma unroll
    for (int mf = 0; mf < 4; mf++) {
        int r0 = s0 + wm * 64 + mf * 16 + (lane >> 2);
        #pragma unroll
        for (int nf = 0; nf < 4; nf++) {
            int co = wn * 32 + nf * 8 + (lane & 3) * 2;
            #pragma unroll
            for (int h = 0; h < 2; h++) {
                int s = r0 + h * 8;
                int y = s >> 6, xx = s & 63;
                float* dst = g_t + ((((size_t)(b * 64 + y)) * 9 + t) * 64 + xx) * COUT + co;
                *(float2*)dst = make_float2(acc[mf][nf][h * 2], acc[mf][nf][h * 2 + 1]);
            }
        }
    }
}

// ---------------------------------------------------------------------------
// Stage 4: tap combine -> phase planes (covers borders; no atomics).
// ---------------------------------------------------------------------------
__global__ __launch_bounds__(256)
void k_comb() {
    int m = blockIdx.x;            // 0..64
    int b = blockIdx.y;
    int tid = threadIdx.x;
    int co = tid & 127;
    int nh = tid >> 7;
    const float* Ty  = g_t + ((size_t)(b * 64 + m) * 9) * 64 * COUT;
    const float* Tym = g_t + ((size_t)(b * 64 + m - 1) * 9) * 64 * COUT;
    bool hy = (m <= 63), hym = (m >= 1);
    float* ob = g_o + (size_t)(b * COUT + co) * PSTR;

    for (int n = nh; n <= 64; n += 2) {
        bool hx = (n <= 63), hxm = (n >= 1);
        float p0 = 0.f, p1 = 0.f, p2 = 0.f, p3 = 0.f;
        if (hy) {
            if (hx) {
                p0 += __ldg(Ty + ((size_t)(0 * 64 + n)) * COUT + co);
                p1 += __ldg(Ty + ((size_t)(1 * 64 + n)) * COUT + co);
                p2 += __ldg(Ty + ((size_t)(3 * 64 + n)) * COUT + co);
                p3 += __ldg(Ty + ((size_t)(4 * 64 + n)) * COUT + co);
            }
            if (hxm) {
                p0 += __ldg(Ty + ((size_t)(2 * 64 + n - 1)) * COUT + co);
                p2 += __ldg(Ty + ((size_t)(5 * 64 + n - 1)) * COUT + co);
            }
        }
        if (hym) {
            if (hx) {
                p0 += __ldg(Tym + ((size_t)(6 * 64 + n)) * COUT + co);
                p1 += __ldg(Tym + ((size_t)(7 * 64 + n)) * COUT + co);
            }
            if (hxm) p0 += __ldg(Tym + ((size_t)(8 * 64 + n - 1)) * COUT + co);
        }
        ob[0 * PL + m * 68 + n] = p0;
        if (n <= 63) ob[1 * PL + m * 68 + n] = p1;
        if (m <= 63) ob[2 * PL + m * 68 + n] = p2;
        if (m <= 63 && n <= 63) ob[3 * PL + m * 68 + n] = p3;
    }
}

// ---------------------------------------------------------------------------
// Stage 5: separable 4x4 blur from phase planes.
// ---------------------------------------------------------------------------
__global__ __launch_bounds__(256)
void k_blur(float* __restrict__ out) {
    int bc = blockIdx.x;
    int u0 = blockIdx.y * 16;
    __shared__ float os[19][132];
    __shared__ float hs[19][132];
    const float bk[4] = {0.25f, 0.75f, 0.75f, 0.25f};
    const float* src = g_o + (size_t)bc * PSTR;

    for (int idx = threadIdx.x; idx < 19 * 132; idx += 256) {
        int r = idx / 132, c = idx - r * 132;
        int gr = u0 - 1 + r, gc = c - 1;
        float v = 0.f;
        if ((unsigned)gr < 129u && (unsigned)gc < 129u) {
            int plane = ((gr & 1) << 1) | (gc & 1);
            v = src[(size_t)plane * PL + (gr >> 1) * 68 + (gc >> 1)];
        }
        os[r][c] = v;
    }
    __syncthreads();
    for (int idx = threadIdx.x; idx < 19 * 128; idx += 256) {
        int r = idx >> 7, v = idx & 127;
        float h = 0.f;
        #pragma unroll
        for (int s = 0; s < 4; s++) h += bk[s] * os[r][v + 3 - s];
        hs[r][v] = h;
    }
    __syncthreads();
    for (int idx = threadIdx.x; idx < 16 * 128; idx += 256) {
        int ul = idx >> 7, v = idx & 127;
        float o = 0.f;
        #pragma unroll
        for (int t = 0; t < 4; t++) o += bk[t] * hs[ul + 3 - t][v];
        out[((size_t)bc * HOUT + u0 + ul) * HOUT + v] = o;
    }
}

// ---------------------------------------------------------------------------
extern "C" void kernel_launch(void* const* d_in, const int* in_sizes, int n_in,
                              void* d_out, int out_size) {
    const float* x      = (const float*)d_in[0];
    const float* style  = (const float*)d_in[1];
    const float* weight = (const float*)d_in[2];
    const float* mod_w  = (const float*)d_in[3];
    const float* mod_b  = (const float*)d_in[4];
    float* out = (float*)d_out;

    cudaFuncSetAttribute(k_gemm, cudaFuncAttributeMaxDynamicSharedMemorySize, 8 * TILE * 2);

    k_style<<<B, 256>>>(style, mod_w, mod_b);
    k_xprep<<<dim3(32, B), 256>>>(x);
    k_wprep<<<dim3(COUT, B), 256>>>(weight);
    k_gemm<<<dim3(32, 9, B), 256, 8 * TILE * 2>>>();
    k_comb<<<dim3(65, B), 256>>>();
    k_blur<<<dim3(B * COUT, 8), 256>>>(out);
}

// round 10
// speedup vs baseline: 3.3474x; 1.5221x over previous
#include <cuda_runtime.h>
#include <cuda_bf16.h>

#define B    16
#define CIN  256
#define COUT 128
#define SDIM 512
#define HOUT 128
#define PL   4420          // 65*68 padded phase plane
#define PSTR (4*PL)
#define OTOT ((size_t)B * COUT * PSTR)

typedef unsigned long long u64;
typedef unsigned int u32;

// Scratch
__device__ float g_s[B * CIN];
__device__ __align__(128) float g_o[OTOT];
__device__ __align__(128) __nv_bfloat16 g_wh[(size_t)B * 9 * COUT * CIN];
__device__ __align__(128) __nv_bfloat16 g_wl[(size_t)B * 9 * COUT * CIN];
__device__ __align__(128) __nv_bfloat16 g_xh[(size_t)B * 4096 * CIN];  // [b][s][ci]
__device__ __align__(128) __nv_bfloat16 g_xl[(size_t)B * 4096 * CIN];

__device__ __forceinline__ u32 su32(const void* p) {
    return (u32)__cvta_generic_to_shared(p);
}
__device__ __forceinline__ void cpa16s(u32 dst, const void* src) {
    asm volatile("cp.async.ca.shared.global [%0],[%1],16;\n" :: "r"(dst), "l"(src));
}
__device__ __forceinline__ void cp_commit() { asm volatile("cp.async.commit_group;"); }

__device__ __forceinline__ void ldm_x4(u32* r, u32 addr) {
    asm volatile("ldmatrix.sync.aligned.m8n8.x4.shared.b16 {%0,%1,%2,%3}, [%4];"
                 : "=r"(r[0]), "=r"(r[1]), "=r"(r[2]), "=r"(r[3]) : "r"(addr));
}
__device__ __forceinline__ void mma_bf16(float* d, const u32* a, u32 b0, u32 b1) {
    asm volatile("mma.sync.aligned.m16n8k16.row.col.f32.bf16.bf16.f32 "
                 "{%0,%1,%2,%3},{%4,%5,%6,%7},{%8,%9},{%0,%1,%2,%3};"
                 : "+f"(d[0]), "+f"(d[1]), "+f"(d[2]), "+f"(d[3])
                 : "r"(a[0]), "r"(a[1]), "r"(a[2]), "r"(a[3]), "r"(b0), "r"(b1));
}
__device__ __forceinline__ void redadd(float* p, float v) {
    asm volatile("red.global.add.f32 [%0], %1;" :: "l"(p), "f"(v) : "memory");
}

// ---------------------------------------------------------------------------
// Stage 0: zero phase planes (atomic accumulation target; graph-replay safe)
// ---------------------------------------------------------------------------
__global__ __launch_bounds__(256)
void k_zero() {
    size_t i = ((size_t)blockIdx.x * 256 + threadIdx.x) * 4;
    if (i < OTOT) *(float4*)(g_o + i) = make_float4(0.f, 0.f, 0.f, 0.f);
}

// ---------------------------------------------------------------------------
// Stage 1: s[b,ci] = style . mod_w^T + mod_b
// ---------------------------------------------------------------------------
__global__ void k_style(const float* __restrict__ style,
                        const float* __restrict__ mod_w,
                        const float* __restrict__ mod_b) {
    int b = blockIdx.x;
    int warp = threadIdx.x >> 5, lane = threadIdx.x & 31;
    const float* st = style + b * SDIM;
    for (int ci = warp; ci < CIN; ci += 8) {
        const float* mw = mod_w + ci * SDIM;
        float sum = 0.f;
        for (int k = lane; k < SDIM; k += 32) sum += st[k] * mw[k];
        #pragma unroll
        for (int off = 16; off; off >>= 1)
            sum += __shfl_down_sync(0xffffffffu, sum, off);
        if (lane == 0) g_s[b * CIN + ci] = sum + mod_b[ci];
    }
}

// ---------------------------------------------------------------------------
// Stage 2: modulate + demodulate -> bf16 hi/lo weights [b][tap][co][ci]
// ---------------------------------------------------------------------------
__global__ void k_wprep(const float* __restrict__ weight) {
    int co = blockIdx.x, b = blockIdx.y;
    __shared__ float vbuf[CIN * 9];
    __shared__ float red[256];
    const float scale = 1.0f / 48.0f;

    float part = 0.f;
    for (int idx = threadIdx.x; idx < CIN * 9; idx += 256) {
        int ci = idx / 9;
        float v = scale * weight[co * CIN * 9 + idx] * g_s[b * CIN + ci];
        vbuf[idx] = v;
        part += v * v;
    }
    red[threadIdx.x] = part;
    __syncthreads();
    for (int s = 128; s; s >>= 1) {
        if (threadIdx.x < s) red[threadIdx.x] += red[threadIdx.x + s];
        __syncthreads();
    }
    float demod = rsqrtf(red[0] + 1e-8f);
    for (int idx = threadIdx.x; idx < CIN * 9; idx += 256) {
        int ci = idx / 9, t = idx - ci * 9;
        float v = vbuf[idx] * demod;
        __nv_bfloat16 hi = __float2bfloat16(v);
        __nv_bfloat16 lo = __float2bfloat16(v - __bfloat162float(hi));
        size_t o = (((size_t)b * 9 + t) * COUT + co) * CIN + ci;
        g_wh[o] = hi;
        g_wl[o] = lo;
    }
}

// ---------------------------------------------------------------------------
// Stage 2b: transpose x -> [b][spatial][ci] bf16 hi/lo, packed u32 stores
// ---------------------------------------------------------------------------
__global__ __launch_bounds__(256)
void k_xprep(const float* __restrict__ x) {
    __shared__ float tile[32][129];
    int sc0 = blockIdx.x * 128;
    int b   = blockIdx.y;
    int tid = threadIdx.x;
    for (int ci0 = 0; ci0 < CIN; ci0 += 32) {
        __syncthreads();
        for (int i = tid; i < 32 * 128; i += 256) {
            int cir = i >> 7, sc = i & 127;
            tile[cir][sc] = x[((size_t)(b * CIN + ci0 + cir)) * 4096 + sc0 + sc];
        }
        __syncthreads();
        for (int it = tid; it < 128 * 16; it += 256) {
            int sc = it >> 4, cu = it & 15;
            float v0 = tile[cu * 2][sc], v1 = tile[cu * 2 + 1][sc];
            __nv_bfloat16 h0 = __float2bfloat16(v0);
            __nv_bfloat16 h1 = __float2bfloat16(v1);
            __nv_bfloat16 l0 = __float2bfloat16(v0 - __bfloat162float(h0));
            __nv_bfloat16 l1 = __float2bfloat16(v1 - __bfloat162float(h1));
            size_t rowo = ((size_t)b * 4096 + sc0 + sc) * CIN + ci0;
            __nv_bfloat162 hp; hp.x = h0; hp.y = h1;
            __nv_bfloat162 lp; lp.x = l0; lp.y = l1;
            ((__nv_bfloat162*)(g_xh + rowo))[cu] = hp;
            ((__nv_bfloat162*)(g_xl + rowo))[cu] = lp;
        }
    }
}

// ---------------------------------------------------------------------------
// Stage 3: warp-MMA GEMM with direct atomic scatter into phase planes.
// Block = (mtile 128 spatial, tap, b). For tap (ky,kx), element (s=y*64+x, co)
// adds into plane=(ky&1)*2+(kx&1) at (m,n)=(y+(ky>>1), x+(kx>>1)).
// ---------------------------------------------------------------------------
#define TILE 5120   // elems per buffer (128*40)
__global__ __launch_bounds__(256)
void k_gemm() {
    extern __shared__ __nv_bfloat16 sm[];
    __nv_bfloat16* Ah = sm;
    __nv_bfloat16* Al = sm + 2 * TILE;
    __nv_bfloat16* Bh = sm + 4 * TILE;
    __nv_bfloat16* Bl = sm + 6 * TILE;

    int mt = blockIdx.x, t = blockIdx.y, b = blockIdx.z;
    int s0 = mt * 128;
    int tid = threadIdx.x, wid = tid >> 5, lane = tid & 31;
    int wm = wid & 1, wn = wid >> 1;

    const __nv_bfloat16* xh = g_xh + ((size_t)b * 4096 + s0) * CIN;
    const __nv_bfloat16* xl = g_xl + ((size_t)b * 4096 + s0) * CIN;
    const __nv_bfloat16* wh = g_wh + ((size_t)b * 9 + t) * COUT * CIN;
    const __nv_bfloat16* wl = g_wl + ((size_t)b * 9 + t) * COUT * CIN;

    float acc[4][4][4];
    #pragma unroll
    for (int i = 0; i < 4; i++)
        #pragma unroll
        for (int j = 0; j < 4; j++)
            #pragma unroll
            for (int k = 0; k < 4; k++) acc[i][j][k] = 0.f;

    auto issue = [&](int c, int buf) {
        int k0 = c * 32;
        #pragma unroll
        for (int i = 0; i < 2; i++) {
            int id = tid * 2 + i;
            int row = id >> 2, seg = id & 3;
            size_t go = (size_t)row * CIN + k0 + seg * 8;
            u32 so = buf * TILE + row * 40 + seg * 8;
            cpa16s(su32(Ah + so), xh + go);
            cpa16s(su32(Al + so), xl + go);
            cpa16s(su32(Bh + so), wh + go);
            cpa16s(su32(Bl + so), wl + go);
        }
        cp_commit();
    };

    issue(0, 0);
    int cur = 0;
    #pragma unroll 1
    for (int c = 0; c < 8; c++) {
        if (c < 7) {
            issue(c + 1, cur ^ 1);
            asm volatile("cp.async.wait_group 1;");
        } else {
            asm volatile("cp.async.wait_group 0;");
        }
        __syncthreads();

        #pragma unroll
        for (int ks = 0; ks < 2; ks++) {
            u32 bh[2][4], bl[2][4];
            #pragma unroll
            for (int ng = 0; ng < 2; ng++) {
                int row = wn * 32 + ng * 16 + (lane & 7) + ((lane & 16) ? 8 : 0);
                int col = ks * 16 + ((lane & 8) ? 8 : 0);
                u32 so = cur * TILE + row * 40 + col;
                ldm_x4(bh[ng], su32(Bh + so));
                ldm_x4(bl[ng], su32(Bl + so));
            }
            #pragma unroll
            for (int mf = 0; mf < 4; mf++) {
                int row = wm * 64 + mf * 16 + (lane & 15);
                int col = ks * 16 + ((lane & 16) ? 8 : 0);
                u32 so = cur * TILE + row * 40 + col;
                u32 ah[4], al[4];
                ldm_x4(ah, su32(Ah + so));
                ldm_x4(al, su32(Al + so));
                #pragma unroll
                for (int ng = 0; ng < 2; ng++) {
                    mma_bf16(acc[mf][ng * 2 + 0], ah, bh[ng][0], bh[ng][1]);
                    mma_bf16(acc[mf][ng * 2 + 1], ah, bh[ng][2], bh[ng][3]);
                    mma_bf16(acc[mf][ng * 2 + 0], al, bh[ng][0], bh[ng][1]);
                    mma_bf16(acc[mf][ng * 2 + 1], al, bh[ng][2], bh[ng][3]);
                    mma_bf16(acc[mf][ng * 2 + 0], ah, bl[ng][0], bl[ng][1]);
                    mma_bf16(acc[mf][ng * 2 + 1], ah, bl[ng][2], bl[ng][3]);
                }
            }
        }
        __syncthreads();
        cur ^= 1;
    }

    // epilogue: atomic scatter into phase plane
    const int ky = t / 3, kx = t - ky * 3;
    const int dm = ky >> 1, dn = kx >> 1;
    const int plane = (ky & 1) * 2 + (kx & 1);
    #pragma unroll
    for (int mf = 0; mf < 4; mf++) {
        int r0 = s0 + wm * 64 + mf * 16 + (lane >> 2);
        #pragma unroll
        for (int nf = 0; nf < 4; nf++) {
            int co = wn * 32 + nf * 8 + (lane & 3) * 2;
            float* dst0 = g_o + (size_t)(b * COUT + co) * PSTR + plane * PL;
            #pragma unroll
            for (int h = 0; h < 2; h++) {
                int s = r0 + h * 8;
                int off = (s >> 6) * 68 + (s & 63) + dm * 68 + dn;
                redadd(dst0 + off, acc[mf][nf][h * 2]);
                redadd(dst0 + PSTR + off, acc[mf][nf][h * 2 + 1]);
            }
        }
    }
}

// ---------------------------------------------------------------------------
// Stage 5: separable 4x4 blur from phase planes.
// ---------------------------------------------------------------------------
__global__ __launch_bounds__(256)
void k_blur(float* __restrict__ out) {
    int bc = blockIdx.x;
    int u0 = blockIdx.y * 16;
    __shared__ float os[19][132];
    __shared__ float hs[19][132];
    const float bk[4] = {0.25f, 0.75f, 0.75f, 0.25f};
    const float* src = g_o + (size_t)bc * PSTR;

    for (int idx = threadIdx.x; idx < 19 * 132; idx += 256) {
        int r = idx / 132, c = idx - r * 132;
        int gr = u0 - 1 + r, gc = c - 1;
        float v = 0.f;
        if ((unsigned)gr < 129u && (unsigned)gc < 129u) {
            int plane = ((gr & 1) << 1) | (gc & 1);
            v = src[(size_t)plane * PL + (gr >> 1) * 68 + (gc >> 1)];
        }
        os[r][c] = v;
    }
    __syncthreads();
    for (int idx = threadIdx.x; idx < 19 * 128; idx += 256) {
        int r = idx >> 7, v = idx & 127;
        float h = 0.f;
        #pragma unroll
        for (int s = 0; s < 4; s++) h += bk[s] * os[r][v + 3 - s];
        hs[r][v] = h;
    }
    __syncthreads();
    for (int idx = threadIdx.x; idx < 16 * 128; idx += 256) {
        int ul = idx >> 7, v = idx & 127;
        float o = 0.f;
        #pragma unroll
        for (int t = 0; t < 4; t++) o += bk[t] * hs[ul + 3 - t][v];
        out[((size_t)bc * HOUT + u0 + ul) * HOUT + v] = o;
    }
}

// ---------------------------------------------------------------------------
extern "C" void kernel_launch(void* const* d_in, const int* in_sizes, int n_in,
                              void* d_out, int out_size) {
    const float* x      = (const float*)d_in[0];
    const float* style  = (const float*)d_in[1];
    const float* weight = (const float*)d_in[2];
    const float* mod_w  = (const float*)d_in[3];
    const float* mod_b  = (const float*)d_in[4];
    float* out = (float*)d_out;

    cudaFuncSetAttribute(k_gemm, cudaFuncAttributeMaxDynamicSharedMemorySize, 8 * TILE * 2);

    k_zero<<<(unsigned)((OTOT / 4 + 255) / 256), 256>>>();
    k_style<<<B, 256>>>(style, mod_w, mod_b);
    k_xprep<<<dim3(32, B), 256>>>(x);
    k_wprep<<<dim3(COUT, B), 256>>>(weight);
    k_gemm<<<dim3(32, 9, B), 256, 8 * TILE * 2>>>();
    k_blur<<<dim3(B * COUT, 8), 256>>>(out);
}

// round 11
// speedup vs baseline: 4.1184x; 1.2303x over previous
#include <cuda_runtime.h>
#include <cuda_fp16.h>

#define B    16
#define CIN  256
#define COUT 128
#define SDIM 512
#define HOUT 128
#define PL   4420          // 65*68 padded phase plane
#define PSTR (4*PL)
#define OTOT ((size_t)B * COUT * PSTR)

typedef unsigned long long u64;
typedef unsigned int u32;

// Scratch
__device__ float g_s[B * CIN];
__device__ __align__(128) float g_o[OTOT];
__device__ __align__(128) __half g_wh[(size_t)B * 9 * COUT * CIN];     // [b][tap][co][ci]
__device__ __align__(128) __half g_xh[(size_t)B * 4096 * CIN];         // [b][s][ci]
__device__ __align__(128) __half g_xl[(size_t)B * 4096 * CIN];

__device__ __forceinline__ u32 su32(const void* p) {
    return (u32)__cvta_generic_to_shared(p);
}
__device__ __forceinline__ void cpa16s(u32 dst, const void* src) {
    asm volatile("cp.async.ca.shared.global [%0],[%1],16;\n" :: "r"(dst), "l"(src));
}
__device__ __forceinline__ void cp_commit() { asm volatile("cp.async.commit_group;"); }

__device__ __forceinline__ void ldm_x4(u32* r, u32 addr) {
    asm volatile("ldmatrix.sync.aligned.m8n8.x4.shared.b16 {%0,%1,%2,%3}, [%4];"
                 : "=r"(r[0]), "=r"(r[1]), "=r"(r[2]), "=r"(r[3]) : "r"(addr));
}
__device__ __forceinline__ void mma_f16(float* d, const u32* a, u32 b0, u32 b1) {
    asm volatile("mma.sync.aligned.m16n8k16.row.col.f32.f16.f16.f32 "
                 "{%0,%1,%2,%3},{%4,%5,%6,%7},{%8,%9},{%0,%1,%2,%3};"
                 : "+f"(d[0]), "+f"(d[1]), "+f"(d[2]), "+f"(d[3])
                 : "r"(a[0]), "r"(a[1]), "r"(a[2]), "r"(a[3]), "r"(b0), "r"(b1));
}
__device__ __forceinline__ void redadd(float* p, float v) {
    asm volatile("red.global.add.f32 [%0], %1;" :: "l"(p), "f"(v) : "memory");
}

// ---------------------------------------------------------------------------
// Stage 0: zero phase planes (atomic accumulation target; graph-replay safe)
// ---------------------------------------------------------------------------
__global__ __launch_bounds__(256)
void k_zero() {
    size_t i = ((size_t)blockIdx.x * 256 + threadIdx.x) * 4;
    if (i < OTOT) *(float4*)(g_o + i) = make_float4(0.f, 0.f, 0.f, 0.f);
}

// ---------------------------------------------------------------------------
// Stage 1: s[b,ci] = style . mod_w^T + mod_b
// ---------------------------------------------------------------------------
__global__ void k_style(const float* __restrict__ style,
                        const float* __restrict__ mod_w,
                        const float* __restrict__ mod_b) {
    int b = blockIdx.x;
    int warp = threadIdx.x >> 5, lane = threadIdx.x & 31;
    const float* st = style + b * SDIM;
    for (int ci = warp; ci < CIN; ci += 8) {
        const float* mw = mod_w + ci * SDIM;
        float sum = 0.f;
        for (int k = lane; k < SDIM; k += 32) sum += st[k] * mw[k];
        #pragma unroll
        for (int off = 16; off; off >>= 1)
            sum += __shfl_down_sync(0xffffffffu, sum, off);
        if (lane == 0) g_s[b * CIN + ci] = sum + mod_b[ci];
    }
}

// ---------------------------------------------------------------------------
// Stage 2: modulate + demodulate -> fp16 weights [b][tap][co][ci]
// ---------------------------------------------------------------------------
__global__ void k_wprep(const float* __restrict__ weight) {
    int co = blockIdx.x, b = blockIdx.y;
    __shared__ float vbuf[CIN * 9];
    __shared__ float red[256];
    const float scale = 1.0f / 48.0f;

    float part = 0.f;
    for (int idx = threadIdx.x; idx < CIN * 9; idx += 256) {
        int ci = idx / 9;
        float v = scale * weight[co * CIN * 9 + idx] * g_s[b * CIN + ci];
        vbuf[idx] = v;
        part += v * v;
    }
    red[threadIdx.x] = part;
    __syncthreads();
    for (int s = 128; s; s >>= 1) {
        if (threadIdx.x < s) red[threadIdx.x] += red[threadIdx.x + s];
        __syncthreads();
    }
    float demod = rsqrtf(red[0] + 1e-8f);
    for (int idx = threadIdx.x; idx < CIN * 9; idx += 256) {
        int ci = idx / 9, t = idx - ci * 9;
        float v = vbuf[idx] * demod;
        g_wh[(((size_t)b * 9 + t) * COUT + co) * CIN + ci] = __float2half_rn(v);
    }
}

// ---------------------------------------------------------------------------
// Stage 2b: transpose x -> [b][spatial][ci] fp16 hi/lo (x = xh + xl)
// ---------------------------------------------------------------------------
__global__ __launch_bounds__(256)
void k_xprep(const float* __restrict__ x) {
    __shared__ float tile[32][129];
    int sc0 = blockIdx.x * 128;
    int b   = blockIdx.y;
    int tid = threadIdx.x;
    for (int ci0 = 0; ci0 < CIN; ci0 += 32) {
        __syncthreads();
        for (int i = tid; i < 32 * 128; i += 256) {
            int cir = i >> 7, sc = i & 127;
            tile[cir][sc] = x[((size_t)(b * CIN + ci0 + cir)) * 4096 + sc0 + sc];
        }
        __syncthreads();
        for (int it = tid; it < 128 * 16; it += 256) {
            int sc = it >> 4, cu = it & 15;
            float v0 = tile[cu * 2][sc], v1 = tile[cu * 2 + 1][sc];
            __half h0 = __float2half_rn(v0);
            __half h1 = __float2half_rn(v1);
            __half l0 = __float2half_rn(v0 - __half2float(h0));
            __half l1 = __float2half_rn(v1 - __half2float(h1));
            size_t rowo = ((size_t)b * 4096 + sc0 + sc) * CIN + ci0;
            __half2 hp; hp.x = h0; hp.y = h1;
            __half2 lp; lp.x = l0; lp.y = l1;
            ((__half2*)(g_xh + rowo))[cu] = hp;
            ((__half2*)(g_xl + rowo))[cu] = lp;
        }
    }
}

// ---------------------------------------------------------------------------
// Stage 3: warp-MMA GEMM (fp16 2-product: xh*wh + xl*wh) with atomic scatter.
// Block = (mtile 128 spatial, tap, b). For tap (ky,kx), element (s, co) adds
// into plane=(ky&1)*2+(kx&1) at (m,n)=(y+(ky>>1), x+(kx>>1)).
// ---------------------------------------------------------------------------
#define TILE 5120   // elems per buffer (128*40)
__global__ __launch_bounds__(256)
void k_gemm() {
    extern __shared__ __half sm[];
    __half* Ah = sm;
    __half* Al = sm + 2 * TILE;
    __half* Bh = sm + 4 * TILE;

    int mt = blockIdx.x, t = blockIdx.y, b = blockIdx.z;
    int s0 = mt * 128;
    int tid = threadIdx.x, wid = tid >> 5, lane = tid & 31;
    int wm = wid & 1, wn = wid >> 1;

    const __half* xh = g_xh + ((size_t)b * 4096 + s0) * CIN;
    const __half* xl = g_xl + ((size_t)b * 4096 + s0) * CIN;
    const __half* wh = g_wh + ((size_t)b * 9 + t) * COUT * CIN;

    float acc[4][4][4];
    #pragma unroll
    for (int i = 0; i < 4; i++)
        #pragma unroll
        for (int j = 0; j < 4; j++)
            #pragma unroll
            for (int k = 0; k < 4; k++) acc[i][j][k] = 0.f;

    auto issue = [&](int c, int buf) {
        int k0 = c * 32;
        #pragma unroll
        for (int i = 0; i < 2; i++) {
            int id = tid * 2 + i;
            int row = id >> 2, seg = id & 3;
            size_t go = (size_t)row * CIN + k0 + seg * 8;
            u32 so = buf * TILE + row * 40 + seg * 8;
            cpa16s(su32(Ah + so), xh + go);
            cpa16s(su32(Al + so), xl + go);
            cpa16s(su32(Bh + so), wh + go);
        }
        cp_commit();
    };

    issue(0, 0);
    int cur = 0;
    #pragma unroll 1
    for (int c = 0; c < 8; c++) {
        if (c < 7) {
            issue(c + 1, cur ^ 1);
            asm volatile("cp.async.wait_group 1;");
        } else {
            asm volatile("cp.async.wait_group 0;");
        }
        __syncthreads();

        #pragma unroll
        for (int ks = 0; ks < 2; ks++) {
            u32 bh[2][4];
            #pragma unroll
            for (int ng = 0; ng < 2; ng++) {
                int row = wn * 32 + ng * 16 + (lane & 7) + ((lane & 16) ? 8 : 0);
                int col = ks * 16 + ((lane & 8) ? 8 : 0);
                ldm_x4(bh[ng], su32(Bh + cur * TILE + row * 40 + col));
            }
            #pragma unroll
            for (int mf = 0; mf < 4; mf++) {
                int row = wm * 64 + mf * 16 + (lane & 15);
                int col = ks * 16 + ((lane & 16) ? 8 : 0);
                u32 so = cur * TILE + row * 40 + col;
                u32 ah[4], al[4];
                ldm_x4(ah, su32(Ah + so));
                ldm_x4(al, su32(Al + so));
                #pragma unroll
                for (int ng = 0; ng < 2; ng++) {
                    mma_f16(acc[mf][ng * 2 + 0], ah, bh[ng][0], bh[ng][1]);
                    mma_f16(acc[mf][ng * 2 + 1], ah, bh[ng][2], bh[ng][3]);
                    mma_f16(acc[mf][ng * 2 + 0], al, bh[ng][0], bh[ng][1]);
                    mma_f16(acc[mf][ng * 2 + 1], al, bh[ng][2], bh[ng][3]);
                }
            }
        }
        __syncthreads();
        cur ^= 1;
    }

    // epilogue: atomic scatter into phase plane
    const int ky = t / 3, kx = t - ky * 3;
    const int dm = ky >> 1, dn = kx >> 1;
    const int plane = (ky & 1) * 2 + (kx & 1);
    #pragma unroll
    for (int mf = 0; mf < 4; mf++) {
        int r0 = s0 + wm * 64 + mf * 16 + (lane >> 2);
        #pragma unroll
        for (int nf = 0; nf < 4; nf++) {
            int co = wn * 32 + nf * 8 + (lane & 3) * 2;
            float* dst0 = g_o + (size_t)(b * COUT + co) * PSTR + plane * PL;
            #pragma unroll
            for (int h = 0; h < 2; h++) {
                int s = r0 + h * 8;
                int off = (s >> 6) * 68 + (s & 63) + dm * 68 + dn;
                redadd(dst0 + off, acc[mf][nf][h * 2]);
                redadd(dst0 + PSTR + off, acc[mf][nf][h * 2 + 1]);
            }
        }
    }
}

// ---------------------------------------------------------------------------
// Stage 5: separable 4x4 blur from phase planes.
// ---------------------------------------------------------------------------
__global__ __launch_bounds__(256)
void k_blur(float* __restrict__ out) {
    int bc = blockIdx.x;
    int u0 = blockIdx.y * 16;
    __shared__ float os[19][132];
    __shared__ float hs[19][132];
    const float bk[4] = {0.25f, 0.75f, 0.75f, 0.25f};
    const float* src = g_o + (size_t)bc * PSTR;

    for (int idx = threadIdx.x; idx < 19 * 132; idx += 256) {
        int r = idx / 132, c = idx - r * 132;
        int gr = u0 - 1 + r, gc = c - 1;
        float v = 0.f;
        if ((unsigned)gr < 129u && (unsigned)gc < 129u) {
            int plane = ((gr & 1) << 1) | (gc & 1);
            v = src[(size_t)plane * PL + (gr >> 1) * 68 + (gc >> 1)];
        }
        os[r][c] = v;
    }
    __syncthreads();
    for (int idx = threadIdx.x; idx < 19 * 128; idx += 256) {
        int r = idx >> 7, v = idx & 127;
        float h = 0.f;
        #pragma unroll
        for (int s = 0; s < 4; s++) h += bk[s] * os[r][v + 3 - s];
        hs[r][v] = h;
    }
    __syncthreads();
    for (int idx = threadIdx.x; idx < 16 * 128; idx += 256) {
        int ul = idx >> 7, v = idx & 127;
        float o = 0.f;
        #pragma unroll
        for (int t = 0; t < 4; t++) o += bk[t] * hs[ul + 3 - t][v];
        out[((size_t)bc * HOUT + u0 + ul) * HOUT + v] = o;
    }
}

// ---------------------------------------------------------------------------
extern "C" void kernel_launch(void* const* d_in, const int* in_sizes, int n_in,
                              void* d_out, int out_size) {
    const float* x      = (const float*)d_in[0];
    const float* style  = (const float*)d_in[1];
    const float* weight = (const float*)d_in[2];
    const float* mod_w  = (const float*)d_in[3];
    const float* mod_b  = (const float*)d_in[4];
    float* out = (float*)d_out;

    cudaFuncSetAttribute(k_gemm, cudaFuncAttributeMaxDynamicSharedMemorySize, 6 * TILE * 2);

    k_zero<<<(unsigned)((OTOT / 4 + 255) / 256), 256>>>();
    k_style<<<B, 256>>>(style, mod_w, mod_b);
    k_xprep<<<dim3(32, B), 256>>>(x);
    k_wprep<<<dim3(COUT, B), 256>>>(weight);
    k_gemm<<<dim3(32, 9, B), 256, 6 * TILE * 2>>>();
    k_blur<<<dim3(B * COUT, 8), 256>>>(out);
}

// round 12
// speedup vs baseline: 4.9965x; 1.2132x over previous
#include <cuda_runtime.h>
#include <cuda_fp16.h>

#define B    16
#define CIN  256
#define COUT 128
#define SDIM 512
#define HOUT 128
#define PL   4420          // 65*68 padded phase plane
#define PSTR (4*PL)
#define OTOT ((size_t)B * COUT * PSTR)

typedef unsigned long long u64;
typedef unsigned int u32;

// Scratch
__device__ float g_s[B * CIN];
__device__ __align__(128) float g_o[OTOT];
__device__ __align__(128) __half g_wh[(size_t)B * 9 * COUT * CIN];     // [b][tap][co][ci]
__device__ __align__(128) __half g_xh[(size_t)B * 4096 * CIN];         // [b][s][ci]

__device__ __forceinline__ u32 su32(const void* p) {
    return (u32)__cvta_generic_to_shared(p);
}
__device__ __forceinline__ void cpa16s(u32 dst, const void* src) {
    asm volatile("cp.async.ca.shared.global [%0],[%1],16;\n" :: "r"(dst), "l"(src));
}
__device__ __forceinline__ void cp_commit() { asm volatile("cp.async.commit_group;"); }

__device__ __forceinline__ void ldm_x4(u32* r, u32 addr) {
    asm volatile("ldmatrix.sync.aligned.m8n8.x4.shared.b16 {%0,%1,%2,%3}, [%4];"
                 : "=r"(r[0]), "=r"(r[1]), "=r"(r[2]), "=r"(r[3]) : "r"(addr));
}
__device__ __forceinline__ void mma_f16(float* d, const u32* a, u32 b0, u32 b1) {
    asm volatile("mma.sync.aligned.m16n8k16.row.col.f32.f16.f16.f32 "
                 "{%0,%1,%2,%3},{%4,%5,%6,%7},{%8,%9},{%0,%1,%2,%3};"
                 : "+f"(d[0]), "+f"(d[1]), "+f"(d[2]), "+f"(d[3])
                 : "r"(a[0]), "r"(a[1]), "r"(a[2]), "r"(a[3]), "r"(b0), "r"(b1));
}
__device__ __forceinline__ void redadd(float* p, float v) {
    asm volatile("red.global.add.f32 [%0], %1;" :: "l"(p), "f"(v) : "memory");
}

// ---------------------------------------------------------------------------
// Stage 0: zero phase planes (atomic accumulation target; graph-replay safe)
// ---------------------------------------------------------------------------
__global__ __launch_bounds__(256)
void k_zero() {
    size_t i = ((size_t)blockIdx.x * 256 + threadIdx.x) * 4;
    if (i < OTOT) *(float4*)(g_o + i) = make_float4(0.f, 0.f, 0.f, 0.f);
}

// ---------------------------------------------------------------------------
// Stage 1: s[b,ci] = style . mod_w^T + mod_b
// ---------------------------------------------------------------------------
__global__ void k_style(const float* __restrict__ style,
                        const float* __restrict__ mod_w,
                        const float* __restrict__ mod_b) {
    int b = blockIdx.x;
    int warp = threadIdx.x >> 5, lane = threadIdx.x & 31;
    const float* st = style + b * SDIM;
    for (int ci = warp; ci < CIN; ci += 8) {
        const float* mw = mod_w + ci * SDIM;
        float sum = 0.f;
        for (int k = lane; k < SDIM; k += 32) sum += st[k] * mw[k];
        #pragma unroll
        for (int off = 16; off; off >>= 1)
            sum += __shfl_down_sync(0xffffffffu, sum, off);
        if (lane == 0) g_s[b * CIN + ci] = sum + mod_b[ci];
    }
}

// ---------------------------------------------------------------------------
// Stage 2: modulate + demodulate -> fp16 weights [b][tap][co][ci]
// ---------------------------------------------------------------------------
__global__ void k_wprep(const float* __restrict__ weight) {
    int co = blockIdx.x, b = blockIdx.y;
    __shared__ float vbuf[CIN * 9];
    __shared__ float red[256];
    const float scale = 1.0f / 48.0f;

    float part = 0.f;
    for (int idx = threadIdx.x; idx < CIN * 9; idx += 256) {
        int ci = idx / 9;
        float v = scale * weight[co * CIN * 9 + idx] * g_s[b * CIN + ci];
        vbuf[idx] = v;
        part += v * v;
    }
    red[threadIdx.x] = part;
    __syncthreads();
    for (int s = 128; s; s >>= 1) {
        if (threadIdx.x < s) red[threadIdx.x] += red[threadIdx.x + s];
        __syncthreads();
    }
    float demod = rsqrtf(red[0] + 1e-8f);
    for (int idx = threadIdx.x; idx < CIN * 9; idx += 256) {
        int ci = idx / 9, t = idx - ci * 9;
        float v = vbuf[idx] * demod;
        g_wh[(((size_t)b * 9 + t) * COUT + co) * CIN + ci] = __float2half_rn(v);
    }
}

// ---------------------------------------------------------------------------
// Stage 2b: transpose x -> [b][spatial][ci] fp16
// ---------------------------------------------------------------------------
__global__ __launch_bounds__(256)
void k_xprep(const float* __restrict__ x) {
    __shared__ float tile[32][129];
    int sc0 = blockIdx.x * 128;
    int b   = blockIdx.y;
    int tid = threadIdx.x;
    for (int ci0 = 0; ci0 < CIN; ci0 += 32) {
        __syncthreads();
        for (int i = tid; i < 32 * 128; i += 256) {
            int cir = i >> 7, sc = i & 127;
            tile[cir][sc] = x[((size_t)(b * CIN + ci0 + cir)) * 4096 + sc0 + sc];
        }
        __syncthreads();
        for (int it = tid; it < 128 * 16; it += 256) {
            int sc = it >> 4, cu = it & 15;
            __half2 hp;
            hp.x = __float2half_rn(tile[cu * 2][sc]);
            hp.y = __float2half_rn(tile[cu * 2 + 1][sc]);
            size_t rowo = ((size_t)b * 4096 + sc0 + sc) * CIN + ci0;
            ((__half2*)(g_xh + rowo))[cu] = hp;
        }
    }
}

// ---------------------------------------------------------------------------
// Stage 3: warp-MMA GEMM (single fp16 product) with atomic scatter.
// Block = (mtile 128 spatial, tap, b). For tap (ky,kx), element (s, co) adds
// into plane=(ky&1)*2+(kx&1) at (m,n)=(y+(ky>>1), x+(kx>>1)).
// ---------------------------------------------------------------------------
#define TILE 5120   // elems per buffer (128*40)
__global__ __launch_bounds__(256)
void k_gemm() {
    extern __shared__ __half sm[];
    __half* Ah = sm;
    __half* Bh = sm + 2 * TILE;

    int mt = blockIdx.x, t = blockIdx.y, b = blockIdx.z;
    int s0 = mt * 128;
    int tid = threadIdx.x, wid = tid >> 5, lane = tid & 31;
    int wm = wid & 1, wn = wid >> 1;

    const __half* xh = g_xh + ((size_t)b * 4096 + s0) * CIN;
    const __half* wh = g_wh + ((size_t)b * 9 + t) * COUT * CIN;

    float acc[4][4][4];
    #pragma unroll
    for (int i = 0; i < 4; i++)
        #pragma unroll
        for (int j = 0; j < 4; j++)
            #pragma unroll
            for (int k = 0; k < 4; k++) acc[i][j][k] = 0.f;

    auto issue = [&](int c, int buf) {
        int k0 = c * 32;
        #pragma unroll
        for (int i = 0; i < 2; i++) {
            int id = tid * 2 + i;
            int row = id >> 2, seg = id & 3;
            size_t go = (size_t)row * CIN + k0 + seg * 8;
            u32 so = buf * TILE + row * 40 + seg * 8;
            cpa16s(su32(Ah + so), xh + go);
            cpa16s(su32(Bh + so), wh + go);
        }
        cp_commit();
    };

    issue(0, 0);
    int cur = 0;
    #pragma unroll 1
    for (int c = 0; c < 8; c++) {
        if (c < 7) {
            issue(c + 1, cur ^ 1);
            asm volatile("cp.async.wait_group 1;");
        } else {
            asm volatile("cp.async.wait_group 0;");
        }
        __syncthreads();

        #pragma unroll
        for (int ks = 0; ks < 2; ks++) {
            u32 bh[2][4];
            #pragma unroll
            for (int ng = 0; ng < 2; ng++) {
                int row = wn * 32 + ng * 16 + (lane & 7) + ((lane & 16) ? 8 : 0);
                int col = ks * 16 + ((lane & 8) ? 8 : 0);
                ldm_x4(bh[ng], su32(Bh + cur * TILE + row * 40 + col));
            }
            #pragma unroll
            for (int mf = 0; mf < 4; mf++) {
                int row = wm * 64 + mf * 16 + (lane & 15);
                int col = ks * 16 + ((lane & 16) ? 8 : 0);
                u32 ah[4];
                ldm_x4(ah, su32(Ah + cur * TILE + row * 40 + col));
                #pragma unroll
                for (int ng = 0; ng < 2; ng++) {
                    mma_f16(acc[mf][ng * 2 + 0], ah, bh[ng][0], bh[ng][1]);
                    mma_f16(acc[mf][ng * 2 + 1], ah, bh[ng][2], bh[ng][3]);
                }
            }
        }
        __syncthreads();
        cur ^= 1;
    }

    // epilogue: atomic scatter into phase plane
    const int ky = t / 3, kx = t - ky * 3;
    const int dm = ky >> 1, dn = kx >> 1;
    const int plane = (ky & 1) * 2 + (kx & 1);
    #pragma unroll
    for (int mf = 0; mf < 4; mf++) {
        int r0 = s0 + wm * 64 + mf * 16 + (lane >> 2);
        #pragma unroll
        for (int nf = 0; nf < 4; nf++) {
            int co = wn * 32 + nf * 8 + (lane & 3) * 2;
            float* dst0 = g_o + (size_t)(b * COUT + co) * PSTR + plane * PL;
            #pragma unroll
            for (int h = 0; h < 2; h++) {
                int s = r0 + h * 8;
                int off = (s >> 6) * 68 + (s & 63) + dm * 68 + dn;
                redadd(dst0 + off, acc[mf][nf][h * 2]);
                redadd(dst0 + PSTR + off, acc[mf][nf][h * 2 + 1]);
            }
        }
    }
}

// ---------------------------------------------------------------------------
// Stage 5: separable 4x4 blur from phase planes.
// ---------------------------------------------------------------------------
__global__ __launch_bounds__(256)
void k_blur(float* __restrict__ out) {
    int bc = blockIdx.x;
    int u0 = blockIdx.y * 16;
    __shared__ float os[19][132];
    __shared__ float hs[19][132];
    const float bk[4] = {0.25f, 0.75f, 0.75f, 0.25f};
    const float* src = g_o + (size_t)bc * PSTR;

    for (int idx = threadIdx.x; idx < 19 * 132; idx += 256) {
        int r = idx / 132, c = idx - r * 132;
        int gr = u0 - 1 + r, gc = c - 1;
        float v = 0.f;
        if ((unsigned)gr < 129u && (unsigned)gc < 129u) {
            int plane = ((gr & 1) << 1) | (gc & 1);
            v = src[(size_t)plane * PL + (gr >> 1) * 68 + (gc >> 1)];
        }
        os[r][c] = v;
    }
    __syncthreads();
    for (int idx = threadIdx.x; idx < 19 * 128; idx += 256) {
        int r = idx >> 7, v = idx & 127;
        float h = 0.f;
        #pragma unroll
        for (int s = 0; s < 4; s++) h += bk[s] * os[r][v + 3 - s];
        hs[r][v] = h;
    }
    __syncthreads();
    for (int idx = threadIdx.x; idx < 16 * 128; idx += 256) {
        int ul = idx >> 7, v = idx & 127;
        float o = 0.f;
        #pragma unroll
        for (int t = 0; t < 4; t++) o += bk[t] * hs[ul + 3 - t][v];
        out[((size_t)bc * HOUT + u0 + ul) * HOUT + v] = o;
    }
}

// ---------------------------------------------------------------------------
extern "C" void kernel_launch(void* const* d_in, const int* in_sizes, int n_in,
                              void* d_out, int out_size) {
    const float* x      = (const float*)d_in[0];
    const float* style  = (const float*)d_in[1];
    const float* weight = (const float*)d_in[2];
    const float* mod_w  = (const float*)d_in[3];
    const float* mod_b  = (const float*)d_in[4];
    float* out = (float*)d_out;

    cudaFuncSetAttribute(k_gemm, cudaFuncAttributeMaxDynamicSharedMemorySize, 4 * TILE * 2);

    k_zero<<<(unsigned)((OTOT / 4 + 255) / 256), 256>>>();
    k_style<<<B, 256>>>(style, mod_w, mod_b);
    k_xprep<<<dim3(32, B), 256>>>(x);
    k_wprep<<<dim3(COUT, B), 256>>>(weight);
    k_gemm<<<dim3(32, 9, B), 256, 4 * TILE * 2>>>();
    k_blur<<<dim3(B * COUT, 8), 256>>>(out);
}

// round 13
// speedup vs baseline: 5.8096x; 1.1628x over previous
#include <cuda_runtime.h>
#include <cuda_fp16.h>

#define B    16
#define CIN  256
#define COUT 128
#define SDIM 512
#define HOUT 128
#define PL   4420          // 65*68 padded phase plane (per co-pair, in half2 units)
#define PSTR (4*PL)
#define OTOT ((size_t)B * 64 * PSTR * 2)   // halves: [b][co/2][plane][65][68][2]

typedef unsigned long long u64;
typedef unsigned int u32;

// Scratch
__device__ float g_s[B * CIN];
__device__ __align__(128) __half g_o[OTOT];
__device__ __align__(128) __half g_wh[(size_t)B * 9 * COUT * CIN];     // [b][tap][co][ci]
__device__ __align__(128) __half g_xh[(size_t)B * 4096 * CIN];         // [b][s][ci]

__device__ __forceinline__ u32 su32(const void* p) {
    return (u32)__cvta_generic_to_shared(p);
}
__device__ __forceinline__ void cpa16s(u32 dst, const void* src) {
    asm volatile("cp.async.ca.shared.global [%0],[%1],16;\n" :: "r"(dst), "l"(src));
}
__device__ __forceinline__ void cp_commit() { asm volatile("cp.async.commit_group;"); }

__device__ __forceinline__ void ldm_x4(u32* r, u32 addr) {
    asm volatile("ldmatrix.sync.aligned.m8n8.x4.shared.b16 {%0,%1,%2,%3}, [%4];"
                 : "=r"(r[0]), "=r"(r[1]), "=r"(r[2]), "=r"(r[3]) : "r"(addr));
}
__device__ __forceinline__ void mma_f16(float* d, const u32* a, u32 b0, u32 b1) {
    asm volatile("mma.sync.aligned.m16n8k16.row.col.f32.f16.f16.f32 "
                 "{%0,%1,%2,%3},{%4,%5,%6,%7},{%8,%9},{%0,%1,%2,%3};"
                 : "+f"(d[0]), "+f"(d[1]), "+f"(d[2]), "+f"(d[3])
                 : "r"(a[0]), "r"(a[1]), "r"(a[2]), "r"(a[3]), "r"(b0), "r"(b1));
}
__device__ __forceinline__ void redadd_h2(__half* p, float a, float b) {
    __half2 h = __floats2half2_rn(a, b);
    u32 v = *(u32*)&h;
    asm volatile("red.global.add.noftz.f16x2 [%0], %1;" :: "l"(p), "r"(v) : "memory");
}

// ---------------------------------------------------------------------------
// Stage 0: zero phase planes (atomic accumulation target; graph-replay safe)
// ---------------------------------------------------------------------------
__global__ __launch_bounds__(256)
void k_zero() {
    size_t i = ((size_t)blockIdx.x * 256 + threadIdx.x) * 8;
    if (i < OTOT) *(uint4*)(g_o + i) = make_uint4(0, 0, 0, 0);
}

// ---------------------------------------------------------------------------
// Stage 1: s[b,ci] = style . mod_w^T + mod_b
// ---------------------------------------------------------------------------
__global__ void k_style(const float* __restrict__ style,
                        const float* __restrict__ mod_w,
                        const float* __restrict__ mod_b) {
    int b = blockIdx.x;
    int warp = threadIdx.x >> 5, lane = threadIdx.x & 31;
    const float* st = style + b * SDIM;
    for (int ci = warp; ci < CIN; ci += 8) {
        const float* mw = mod_w + ci * SDIM;
        float sum = 0.f;
        for (int k = lane; k < SDIM; k += 32) sum += st[k] * mw[k];
        #pragma unroll
        for (int off = 16; off; off >>= 1)
            sum += __shfl_down_sync(0xffffffffu, sum, off);
        if (lane == 0) g_s[b * CIN + ci] = sum + mod_b[ci];
    }
}

// ---------------------------------------------------------------------------
// Stage 2: modulate + demodulate -> fp16 weights [b][tap][co][ci]
// ---------------------------------------------------------------------------
__global__ void k_wprep(const float* __restrict__ weight) {
    int co = blockIdx.x, b = blockIdx.y;
    __shared__ float vbuf[CIN * 9];
    __shared__ float red[256];
    const float scale = 1.0f / 48.0f;

    float part = 0.f;
    for (int idx = threadIdx.x; idx < CIN * 9; idx += 256) {
        int ci = idx / 9;
        float v = scale * weight[co * CIN * 9 + idx] * g_s[b * CIN + ci];
        vbuf[idx] = v;
        part += v * v;
    }
    red[threadIdx.x] = part;
    __syncthreads();
    for (int s = 128; s; s >>= 1) {
        if (threadIdx.x < s) red[threadIdx.x] += red[threadIdx.x + s];
        __syncthreads();
    }
    float demod = rsqrtf(red[0] + 1e-8f);
    for (int idx = threadIdx.x; idx < CIN * 9; idx += 256) {
        int ci = idx / 9, t = idx - ci * 9;
        float v = vbuf[idx] * demod;
        g_wh[(((size_t)b * 9 + t) * COUT + co) * CIN + ci] = __float2half_rn(v);
    }
}

// ---------------------------------------------------------------------------
// Stage 2b: transpose x -> [b][spatial][ci] fp16
// ---------------------------------------------------------------------------
__global__ __launch_bounds__(256)
void k_xprep(const float* __restrict__ x) {
    __shared__ float tile[32][129];
    int sc0 = blockIdx.x * 128;
    int b   = blockIdx.y;
    int tid = threadIdx.x;
    for (int ci0 = 0; ci0 < CIN; ci0 += 32) {
        __syncthreads();
        for (int i = tid; i < 32 * 128; i += 256) {
            int cir = i >> 7, sc = i & 127;
            tile[cir][sc] = x[((size_t)(b * CIN + ci0 + cir)) * 4096 + sc0 + sc];
        }
        __syncthreads();
        for (int it = tid; it < 128 * 16; it += 256) {
            int sc = it >> 4, cu = it & 15;
            __half2 hp;
            hp.x = __float2half_rn(tile[cu * 2][sc]);
            hp.y = __float2half_rn(tile[cu * 2 + 1][sc]);
            size_t rowo = ((size_t)b * 4096 + sc0 + sc) * CIN + ci0;
            ((__half2*)(g_xh + rowo))[cu] = hp;
        }
    }
}

// ---------------------------------------------------------------------------
// Stage 3: warp-MMA GEMM (single fp16 product) with packed f16x2 atomic scatter.
// Block = (mtile 128 spatial, tap, b). For tap (ky,kx), element (s, co) adds
// into plane=(ky&1)*2+(kx&1) at (m,n)=(y+(ky>>1), x+(kx>>1)).
// ---------------------------------------------------------------------------
#define TILE 5120   // elems per buffer (128*40)
__global__ __launch_bounds__(256)
void k_gemm() {
    extern __shared__ __half sm[];
    __half* Ah = sm;
    __half* Bh = sm + 2 * TILE;

    int mt = blockIdx.x, t = blockIdx.y, b = blockIdx.z;
    int s0 = mt * 128;
    int tid = threadIdx.x, wid = tid >> 5, lane = tid & 31;
    int wm = wid & 1, wn = wid >> 1;

    const __half* xh = g_xh + ((size_t)b * 4096 + s0) * CIN;
    const __half* wh = g_wh + ((size_t)b * 9 + t) * COUT * CIN;

    float acc[4][4][4];
    #pragma unroll
    for (int i = 0; i < 4; i++)
        #pragma unroll
        for (int j = 0; j < 4; j++)
            #pragma unroll
            for (int k = 0; k < 4; k++) acc[i][j][k] = 0.f;

    auto issue = [&](int c, int buf) {
        int k0 = c * 32;
        #pragma unroll
        for (int i = 0; i < 2; i++) {
            int id = tid * 2 + i;
            int row = id >> 2, seg = id & 3;
            size_t go = (size_t)row * CIN + k0 + seg * 8;
            u32 so = buf * TILE + row * 40 + seg * 8;
            cpa16s(su32(Ah + so), xh + go);
            cpa16s(su32(Bh + so), wh + go);
        }
        cp_commit();
    };

    issue(0, 0);
    int cur = 0;
    #pragma unroll 1
    for (int c = 0; c < 8; c++) {
        if (c < 7) {
            issue(c + 1, cur ^ 1);
            asm volatile("cp.async.wait_group 1;");
        } else {
            asm volatile("cp.async.wait_group 0;");
        }
        __syncthreads();

        #pragma unroll
        for (int ks = 0; ks < 2; ks++) {
            u32 bh[2][4];
            #pragma unroll
            for (int ng = 0; ng < 2; ng++) {
                int row = wn * 32 + ng * 16 + (lane & 7) + ((lane & 16) ? 8 : 0);
                int col = ks * 16 + ((lane & 8) ? 8 : 0);
                ldm_x4(bh[ng], su32(Bh + cur * TILE + row * 40 + col));
            }
            #pragma unroll
            for (int mf = 0; mf < 4; mf++) {
                int row = wm * 64 + mf * 16 + (lane & 15);
                int col = ks * 16 + ((lane & 16) ? 8 : 0);
                u32 ah[4];
                ldm_x4(ah, su32(Ah + cur * TILE + row * 40 + col));
                #pragma unroll
                for (int ng = 0; ng < 2; ng++) {
                    mma_f16(acc[mf][ng * 2 + 0], ah, bh[ng][0], bh[ng][1]);
                    mma_f16(acc[mf][ng * 2 + 1], ah, bh[ng][2], bh[ng][3]);
                }
            }
        }
        __syncthreads();
        cur ^= 1;
    }

    // epilogue: packed f16x2 atomic scatter into phase plane pair-layout
    const int ky = t / 3, kx = t - ky * 3;
    const int dm = ky >> 1, dn = kx >> 1;
    const int plane = (ky & 1) * 2 + (kx & 1);
    #pragma unroll
    for (int mf = 0; mf < 4; mf++) {
        int r0 = s0 + wm * 64 + mf * 16 + (lane >> 2);
        #pragma unroll
        for (int nf = 0; nf < 4; nf++) {
            int co = wn * 32 + nf * 8 + (lane & 3) * 2;    // even
            int cp = co >> 1;
            __half* dst0 = g_o + ((size_t)(b * 64 + cp) * PSTR + (size_t)plane * PL) * 2;
            #pragma unroll
            for (int h = 0; h < 2; h++) {
                int s = r0 + h * 8;
                int off = (s >> 6) * 68 + (s & 63) + dm * 68 + dn;
                redadd_h2(dst0 + 2 * off, acc[mf][nf][h * 2], acc[mf][nf][h * 2 + 1]);
            }
        }
    }
}

// ---------------------------------------------------------------------------
// Stage 5: separable 4x4 blur from fp16 phase planes, co-pair per block.
// ---------------------------------------------------------------------------
__global__ __launch_bounds__(256)
void k_blur(float* __restrict__ out) {
    int bc2 = blockIdx.x;              // b*64 + cp
    int u0 = blockIdx.y * 16;
    int b = bc2 >> 6, cp = bc2 & 63;
    __shared__ float2 os[19][132];
    __shared__ float2 hs[19][132];
    const float bk[4] = {0.25f, 0.75f, 0.75f, 0.25f};
    const __half* src = g_o + (size_t)bc2 * PSTR * 2;

    for (int idx = threadIdx.x; idx < 19 * 132; idx += 256) {
        int r = idx / 132, c = idx - r * 132;
        int gr = u0 - 1 + r, gc = c - 1;
        float2 v = make_float2(0.f, 0.f);
        if ((unsigned)gr < 129u && (unsigned)gc < 129u) {
            int plane = ((gr & 1) << 1) | (gc & 1);
            __half2 h = *(const __half2*)(src + 2 * ((size_t)plane * PL + (gr >> 1) * 68 + (gc >> 1)));
            v = __half22float2(h);
        }
        os[r][c] = v;
    }
    __syncthreads();
    for (int idx = threadIdx.x; idx < 19 * 128; idx += 256) {
        int r = idx >> 7, v = idx & 127;
        float2 h = make_float2(0.f, 0.f);
        #pragma unroll
        for (int s = 0; s < 4; s++) {
            float2 o = os[r][v + 3 - s];
            h.x += bk[s] * o.x;
            h.y += bk[s] * o.y;
        }
        hs[r][v] = h;
    }
    __syncthreads();
    size_t ob = ((size_t)(b * COUT + cp * 2)) * HOUT * HOUT;
    for (int idx = threadIdx.x; idx < 16 * 128; idx += 256) {
        int ul = idx >> 7, v = idx & 127;
        float2 o = make_float2(0.f, 0.f);
        #pragma unroll
        for (int t = 0; t < 4; t++) {
            float2 h = hs[ul + 3 - t][v];
            o.x += bk[t] * h.x;
            o.y += bk[t] * h.y;
        }
        size_t at = ob + (size_t)(u0 + ul) * HOUT + v;
        out[at] = o.x;
        out[at + (size_t)HOUT * HOUT] = o.y;
    }
}

// ---------------------------------------------------------------------------
extern "C" void kernel_launch(void* const* d_in, const int* in_sizes, int n_in,
                              void* d_out, int out_size) {
    const float* x      = (const float*)d_in[0];
    const float* style  = (const float*)d_in[1];
    const float* weight = (const float*)d_in[2];
    const float* mod_w  = (const float*)d_in[3];
    const float* mod_b  = (const float*)d_in[4];
    float* out = (float*)d_out;

    cudaFuncSetAttribute(k_gemm, cudaFuncAttributeMaxDynamicSharedMemorySize, 4 * TILE * 2);

    k_zero<<<(unsigned)((OTOT / 8 + 255) / 256), 256>>>();
    k_style<<<B, 256>>>(style, mod_w, mod_b);
    k_xprep<<<dim3(32, B), 256>>>(x);
    k_wprep<<<dim3(COUT, B), 256>>>(weight);
    k_gemm<<<dim3(32, 9, B), 256, 4 * TILE * 2>>>();
    k_blur<<<dim3(B * 64, 8), 256>>>(out);
}